// round 11
// baseline (speedup 1.0000x reference)
#include <cuda_runtime.h>
#include <cuda_bf16.h>
#include <math.h>
#include <stdint.h>

// ---------------------------------------------------------------------------
// Problem constants
// ---------------------------------------------------------------------------
#define B_      2
#define S_      2048
#define HIDDEN_ 2048
#define NH_     8
#define NKV_    2
#define HD_     256
#define QKV_N   3072          // (8 + 2*2) * 256
#define MROWS   (B_ * S_)     // 4096

// ---------------------------------------------------------------------------
// Scratch (device globals; no allocation allowed)
// ---------------------------------------------------------------------------
__device__ float         g_qkv    [(size_t)MROWS * QKV_N];
__device__ float         g_v      [(size_t)B_ * NKV_ * S_ * HD_];   // fp32 V
__device__ __nv_bfloat16 g_qh     [(size_t)B_ * NH_  * S_ * HD_];
__device__ __nv_bfloat16 g_ql     [(size_t)B_ * NH_  * S_ * HD_];
__device__ __nv_bfloat16 g_kh     [(size_t)B_ * NKV_ * S_ * HD_];
__device__ __nv_bfloat16 g_kl     [(size_t)B_ * NKV_ * S_ * HD_];
__device__ __nv_bfloat16 g_vth    [(size_t)B_ * NKV_ * HD_ * S_];   // V^T [d][s]
__device__ __nv_bfloat16 g_vtl    [(size_t)B_ * NKV_ * HD_ * S_];
__device__ __nv_bfloat16 g_hid_hi [(size_t)MROWS * HIDDEN_];
__device__ __nv_bfloat16 g_hid_lo [(size_t)MROWS * HIDDEN_];
__device__ __nv_bfloat16 g_attn_hi[(size_t)MROWS * (NH_ * HD_)];
__device__ __nv_bfloat16 g_attn_lo[(size_t)MROWS * (NH_ * HD_)];
__device__ __nv_bfloat16 g_wqkT_hi[(size_t)QKV_N * HIDDEN_];
__device__ __nv_bfloat16 g_wqkT_lo[(size_t)QKV_N * HIDDEN_];
__device__ __nv_bfloat16 g_woT_hi [(size_t)HIDDEN_ * (NH_ * HD_)];
__device__ __nv_bfloat16 g_woT_lo [(size_t)HIDDEN_ * (NH_ * HD_)];

// ---------------------------------------------------------------------------
// Helpers
// ---------------------------------------------------------------------------
__device__ __forceinline__ uint32_t smem_u32(const void* p) {
    uint32_t a;
    asm("{ .reg .u64 t; cvta.to.shared.u64 t, %1; cvt.u32.u64 %0, t; }"
        : "=r"(a) : "l"(p));
    return a;
}

#define CP_ASYNC16(sm, gp) \
    asm volatile("cp.async.cg.shared.global [%0], [%1], 16;" \
        :: "r"(sm), "l"(gp) : "memory")
#define CP_COMMIT() asm volatile("cp.async.commit_group;" ::: "memory")
#define CP_WAIT0()  asm volatile("cp.async.wait_group 0;"  ::: "memory")

#define LDMATRIX_X4(r0, r1, r2, r3, addr) \
    asm volatile("ldmatrix.sync.aligned.m8n8.x4.shared.b16 {%0,%1,%2,%3}, [%4];" \
        : "=r"(r0), "=r"(r1), "=r"(r2), "=r"(r3) : "r"(addr))

__device__ __forceinline__ void mma_bf16(
    float& d0, float& d1, float& d2, float& d3,
    uint32_t a0, uint32_t a1, uint32_t a2, uint32_t a3,
    uint32_t b0, uint32_t b1)
{
    asm volatile(
        "mma.sync.aligned.m16n8k16.row.col.f32.bf16.bf16.f32 "
        "{%0,%1,%2,%3}, {%4,%5,%6,%7}, {%8,%9}, {%0,%1,%2,%3};"
        : "+f"(d0), "+f"(d1), "+f"(d2), "+f"(d3)
        : "r"(a0), "r"(a1), "r"(a2), "r"(a3), "r"(b0), "r"(b1));
}

__device__ __forceinline__ void split_bf16(float x, __nv_bfloat16& hi,
                                           __nv_bfloat16& lo) {
    hi = __float2bfloat16_rn(x);
    lo = __float2bfloat16_rn(x - __bfloat162float(hi));
}
__device__ __forceinline__ uint32_t pack2(__nv_bfloat16 lo, __nv_bfloat16 hi) {
    __nv_bfloat162 r;
    r.x = lo; r.y = hi;
    return *(uint32_t*)&r;
}

// ---------------------------------------------------------------------------
// Elementwise fp32 -> (hi, lo) bf16 split. n4 = element count / 4.
// ---------------------------------------------------------------------------
__global__ __launch_bounds__(256) void split_k(
    const float* __restrict__ in, __nv_bfloat16* __restrict__ hi,
    __nv_bfloat16* __restrict__ lo, int n4)
{
    int i = blockIdx.x * 256 + threadIdx.x;
    if (i >= n4) return;
    float4 v = ((const float4*)in)[i];
    __nv_bfloat16 h[4], l[4];
    split_bf16(v.x, h[0], l[0]);
    split_bf16(v.y, h[1], l[1]);
    split_bf16(v.z, h[2], l[2]);
    split_bf16(v.w, h[3], l[3]);
    ((uint2*)hi)[i] = *(uint2*)h;
    ((uint2*)lo)[i] = *(uint2*)l;
}

// ---------------------------------------------------------------------------
// Transpose + split: outHi/outLo[n][k] = split(in[k][n]); in is R x C.
// ---------------------------------------------------------------------------
__global__ __launch_bounds__(256) void transpose_split_k(
    const float* __restrict__ in, __nv_bfloat16* __restrict__ outHi,
    __nv_bfloat16* __restrict__ outLo, int R, int C)
{
    __shared__ float tile[32][33];
    const int tx = threadIdx.x, ty = threadIdx.y;
    const int c0 = blockIdx.x * 32, r0 = blockIdx.y * 32;
#pragma unroll
    for (int i = ty; i < 32; i += 8)
        tile[i][tx] = in[(size_t)(r0 + i) * C + c0 + tx];
    __syncthreads();
#pragma unroll
    for (int i = ty; i < 32; i += 8) {
        __nv_bfloat16 h, l;
        split_bf16(tile[tx][i], h, l);
        outHi[(size_t)(c0 + i) * R + r0 + tx] = h;
        outLo[(size_t)(c0 + i) * R + r0 + tx] = l;
    }
}

// ---------------------------------------------------------------------------
// bf16x3 GEMM: 8 warps, warp tile 64x32, BK=32, ldmatrix fragments,
// NSTAGE=2 (2 CTAs/SM), ONE barrier per chunk (issue-next-after-barrier).
// ---------------------------------------------------------------------------
#define ASTRIDE 40
#define TILE_B  (128 * ASTRIDE * 2)        // 10240 bytes
#define STAGE_B (4 * TILE_B)               // 40960 bytes
#define NSTAGE  2

__global__ __launch_bounds__(256, 2) void gemm_bf16x3_k(
    const __nv_bfloat16* __restrict__ Ahi, const __nv_bfloat16* __restrict__ Alo,
    const __nv_bfloat16* __restrict__ Bhi, const __nv_bfloat16* __restrict__ Blo,
    float* __restrict__ C, int M, int N, int K)
{
    extern __shared__ char dsm[];
    const int t    = threadIdx.x;
    const int lane = t & 31, w = t >> 5;
    const int gid  = lane >> 2, tig = lane & 3;
    const int wm   = (w >> 2) * 64;
    const int wn   = (w & 3) * 32;
    const int brow = blockIdx.y * 128;
    const int bcol = blockIdx.x * 128;

    const uint32_t smBase = smem_u32(dsm);

    const int lm = lane >> 3;              // matrix index 0..3
    const int lr = lane & 7;
    const uint32_t aFragOff =
        (uint32_t)((wm + (lm & 1) * 8 + lr) * 80 + (lm >> 1) * 16);
    const uint32_t bFragOff =
        (uint32_t)((wn + (lm >> 1) * 8 + lr) * 80 + (lm & 1) * 16);

    float acc[16][4];
#pragma unroll
    for (int i = 0; i < 16; i++)
#pragma unroll
        for (int j = 0; j < 4; j++) acc[i][j] = 0.f;

    const int nk = K >> 5;

    auto issue = [&](int s, int kt) {
        const uint32_t st = smBase + s * STAGE_B;
        const int k0 = kt << 5;
        const __nv_bfloat16* srcs[4] = { Ahi, Alo, Bhi, Blo };
        const int rb[4] = { brow, brow, bcol, bcol };
#pragma unroll
        for (int m = 0; m < 4; m++) {
            const uint32_t dst = st + m * TILE_B;
#pragma unroll
            for (int i = 0; i < 2; i++) {
                const int j = i * 256 + t;
                const int r = j >> 2, kq = j & 3;
                CP_ASYNC16(dst + (uint32_t)(r * ASTRIDE + kq * 8) * 2,
                           srcs[m] + (size_t)(rb[m] + r) * K + k0 + kq * 8);
            }
        }
    };

    issue(0, 0); CP_COMMIT();

    for (int kt = 0; kt < nk; kt++) {
        CP_WAIT0();
        __syncthreads();
        // prefetch next chunk into the other buffer; safe because the
        // barrier above ordered all reads of that buffer (iteration kt-1).
        if (kt + 1 < nk) { issue((kt + 1) & 1, kt + 1); CP_COMMIT(); }

        const int buf = kt & 1;
        const uint32_t stBase = smBase + buf * STAGE_B;
        const uint32_t aH = stBase + aFragOff;
        const uint32_t aL = aH + TILE_B;
        const uint32_t bH = stBase + 2 * TILE_B + bFragOff;
        const uint32_t bL = bH + TILE_B;

#pragma unroll
        for (int ks = 0; ks < 2; ks++) {
            const uint32_t kb = (uint32_t)(ks * 32);
            uint32_t ah[4][4], al[4][4];
#pragma unroll
            for (int mt = 0; mt < 4; mt++) {
                LDMATRIX_X4(ah[mt][0], ah[mt][1], ah[mt][2], ah[mt][3],
                            aH + mt * 1280 + kb);
                LDMATRIX_X4(al[mt][0], al[mt][1], al[mt][2], al[mt][3],
                            aL + mt * 1280 + kb);
            }
            uint32_t bh[4][2], bl[4][2];
#pragma unroll
            for (int jj = 0; jj < 2; jj++) {
                uint32_t q0, q1, q2, q3;
                LDMATRIX_X4(q0, q1, q2, q3, bH + jj * 1280 + kb);
                bh[2 * jj][0] = q0; bh[2 * jj][1] = q1;
                bh[2 * jj + 1][0] = q2; bh[2 * jj + 1][1] = q3;
                LDMATRIX_X4(q0, q1, q2, q3, bL + jj * 1280 + kb);
                bl[2 * jj][0] = q0; bl[2 * jj][1] = q1;
                bl[2 * jj + 1][0] = q2; bl[2 * jj + 1][1] = q3;
            }
#pragma unroll
            for (int nt = 0; nt < 4; nt++) {
#pragma unroll
                for (int mt = 0; mt < 4; mt++) {
                    float* d = acc[nt * 4 + mt];
                    mma_bf16(d[0], d[1], d[2], d[3],
                             ah[mt][0], ah[mt][1], ah[mt][2], ah[mt][3],
                             bh[nt][0], bh[nt][1]);
                    mma_bf16(d[0], d[1], d[2], d[3],
                             ah[mt][0], ah[mt][1], ah[mt][2], ah[mt][3],
                             bl[nt][0], bl[nt][1]);
                    mma_bf16(d[0], d[1], d[2], d[3],
                             al[mt][0], al[mt][1], al[mt][2], al[mt][3],
                             bh[nt][0], bh[nt][1]);
                }
            }
        }
        // no trailing barrier: next iteration's top barrier provides ordering.
    }

#pragma unroll
    for (int nt = 0; nt < 4; nt++) {
#pragma unroll
        for (int mt = 0; mt < 4; mt++) {
            const float* d = acc[nt * 4 + mt];
            const int r0 = brow + wm + mt * 16 + gid;
            const int c0 = bcol + wn + nt * 8 + 2 * tig;
            *(float2*)&C[(size_t)r0 * N + c0]       = make_float2(d[0], d[1]);
            *(float2*)&C[(size_t)(r0 + 8) * N + c0] = make_float2(d[2], d[3]);
        }
    }
}

// ---------------------------------------------------------------------------
// Fused per-head RMSNorm (+ RoPE for q/k). Emits bf16 hi/lo for Q and K,
// fp32 for V (V^T split happens in transpose_split_k).
// ---------------------------------------------------------------------------
__global__ __launch_bounds__(256) void qkv_post_k(
    const float* __restrict__ qkv, const int* __restrict__ positions,
    const float* __restrict__ qw, const float* __restrict__ kw,
    __nv_bfloat16* __restrict__ QhO, __nv_bfloat16* __restrict__ QlO,
    __nv_bfloat16* __restrict__ KhO, __nv_bfloat16* __restrict__ KlO,
    float* __restrict__ V)
{
    const int h   = blockIdx.x;   // 0..11
    const int s   = blockIdx.y;
    const int b   = blockIdx.z;
    const int tid = threadIdx.x;  // 0..255

    __shared__ float red[8];
    __shared__ float sy[256];

    const float* row = qkv + (size_t)(b * S_ + s) * QKV_N;

    int off;
    float w = 1.0f;
    if (h < 8)       { off = h * 256;                w = qw[tid]; }
    else if (h < 10) { off = 2048 + (h - 8) * 256;   w = kw[tid]; }
    else             { off = 2560 + (h - 10) * 256; }

    float x = row[off + tid];
    float v = x * x;
#pragma unroll
    for (int o = 16; o > 0; o >>= 1) v += __shfl_xor_sync(0xffffffffu, v, o);
    if ((tid & 31) == 0) red[tid >> 5] = v;
    __syncthreads();
    float ss = 0.f;
#pragma unroll
    for (int i = 0; i < 8; i++) ss += red[i];

    float y = x * rsqrtf(ss * (1.0f / 256.0f) + 1e-6f) * w;

    if (h >= 10) {
        V[((size_t)(b * NKV_ + (h - 10)) * S_ + s) * HD_ + tid] = y;
        return;
    }

    sy[tid] = y;
    __syncthreads();

    if (tid < 128) {
        float invf = powf(1000000.0f, -(float)tid * (1.0f / 128.0f));
        float f    = (float)positions[b * S_ + s] * invf;
        float si, co;
        sincosf(f, &si, &co);
        float x1 = sy[tid];
        float x2 = sy[tid + 128];
        float o1 = x1 * co - x2 * si;
        float o2 = x2 * co + x1 * si;
        __nv_bfloat16 h1, l1, h2, l2;
        split_bf16(o1, h1, l1);
        split_bf16(o2, h2, l2);
        if (h < 8) {
            size_t base = ((size_t)(b * NH_ + h) * S_ + s) * HD_;
            QhO[base + tid] = h1;       QlO[base + tid] = l1;
            QhO[base + tid + 128] = h2; QlO[base + tid + 128] = l2;
        } else {
            size_t base = ((size_t)(b * NKV_ + (h - 8)) * S_ + s) * HD_;
            KhO[base + tid] = h1;       KlO[base + tid] = l1;
            KhO[base + tid + 128] = h2; KlO[base + tid + 128] = l2;
        }
    }
}

// ---------------------------------------------------------------------------
// Flash attention on HMMA with bf16x3 emulation.
// Round-5 tiling (4 warps, 64 q rows, BK=32, double-buffered KV, 1 CTA/SM)
// + ldmatrix fragment loads + ONE barrier per tile + heavy-first scheduling.
// ---------------------------------------------------------------------------
#define QROWB   528                     // bytes per Q/K smem row (264 bf16)
#define VROWB   80                      // bytes per Vt smem row (40 bf16)
#define SM_QH   0
#define SM_QL   33792                   // 64*528
#define SM_ST0  67584
#define STG_B   74752                   // K(16896*2) + Vt(20480*2)
#define ST_KH   0
#define ST_KL   16896
#define ST_VTH  33792
#define ST_VTL  54272
#define ATTN_SMEM_TOTAL (SM_ST0 + 2 * STG_B)   // 217088

__global__ __launch_bounds__(128, 1) void attn_mma_k(
    const __nv_bfloat16* __restrict__ Qh, const __nv_bfloat16* __restrict__ Ql,
    const __nv_bfloat16* __restrict__ Kh, const __nv_bfloat16* __restrict__ Kl,
    const __nv_bfloat16* __restrict__ Vth, const __nv_bfloat16* __restrict__ Vtl,
    __nv_bfloat16* __restrict__ Ohi, __nv_bfloat16* __restrict__ Olo)
{
    extern __shared__ char dsm[];
    const int t    = threadIdx.x;
    const int lane = t & 31, w = t >> 5;
    const int gid  = lane >> 2, tig = lane & 3;
    const int h    = blockIdx.y, b = blockIdx.z;
    const int qt   = gridDim.x - 1 - blockIdx.x;   // heavy tiles first
    const int q0   = qt * 64;
    const int kvh  = h >> 2;
    const uint32_t smb = smem_u32(dsm);

    const __nv_bfloat16* qhg = Qh + ((size_t)(b * NH_ + h) * S_ + q0) * HD_;
    const __nv_bfloat16* qlg = Ql + ((size_t)(b * NH_ + h) * S_ + q0) * HD_;
    const __nv_bfloat16* khg = Kh + (size_t)(b * NKV_ + kvh) * S_ * HD_;
    const __nv_bfloat16* klg = Kl + (size_t)(b * NKV_ + kvh) * S_ * HD_;
    const __nv_bfloat16* vhg = Vth + (size_t)(b * NKV_ + kvh) * HD_ * S_;
    const __nv_bfloat16* vlg = Vtl + (size_t)(b * NKV_ + kvh) * HD_ * S_;

    // ---- stage Q (hi+lo): 64 rows x 256 bf16 each ----
#pragma unroll
    for (int i = 0; i < 16; i++) {
        const int j = i * 128 + t;             // 0..2047
        const int r = j >> 5, c = j & 31;
        CP_ASYNC16(smb + SM_QH + r * QROWB + c * 16, qhg + (size_t)r * HD_ + c * 8);
        CP_ASYNC16(smb + SM_QL + r * QROWB + c * 16, qlg + (size_t)r * HD_ + c * 8);
    }

    const int nt = qt * 2 + 2;                // K-tiles of 32

    auto issueKV = [&](int kt) {
        const uint32_t st = smb + SM_ST0 + (kt & 1) * STG_B;
        const int k0 = kt << 5;
#pragma unroll
        for (int i = 0; i < 8; i++) {
            const int j = i * 128 + t;         // 0..1023
            const int r = j >> 5, c = j & 31;  // K: row, 8-elt chunk
            CP_ASYNC16(st + ST_KH + r * QROWB + c * 16,
                       khg + (size_t)(k0 + r) * HD_ + c * 8);
            CP_ASYNC16(st + ST_KL + r * QROWB + c * 16,
                       klg + (size_t)(k0 + r) * HD_ + c * 8);
            const int vr = j >> 2, vc = j & 3; // Vt: row d, 8-elt chunk
            CP_ASYNC16(st + ST_VTH + vr * VROWB + vc * 16,
                       vhg + (size_t)vr * S_ + k0 + vc * 8);
            CP_ASYNC16(st + ST_VTL + vr * VROWB + vc * 16,
                       vlg + (size_t)vr * S_ + k0 + vc * 8);
        }
    };

    issueKV(0); CP_COMMIT();

    float O[32][4];
#pragma unroll
    for (int n = 0; n < 32; n++)
#pragma unroll
        for (int i = 0; i < 4; i++) O[n][i] = 0.f;
    float m0 = -1e30f, m1 = -1e30f, l0 = 0.f, l1 = 0.f;

    // ldmatrix per-lane offsets
    const int lm = lane >> 3, lr = lane & 7;
    const uint32_t qFragH = smb + SM_QH +
        (uint32_t)((w * 16 + (lm & 1) * 8 + lr) * QROWB + (lm >> 1) * 16);
    const uint32_t qFragL = qFragH + (SM_QL - SM_QH);
    const uint32_t kFragOff =
        (uint32_t)(((lm >> 1) * 8 + lr) * QROWB + (lm & 1) * 16);
    const uint32_t vFragOff =
        (uint32_t)(((lm >> 1) * 8 + lr) * VROWB + (lm & 1) * 16);

    for (int kt = 0; kt < nt; kt++) {
        CP_WAIT0();
        __syncthreads();
        // prefetch next KV tile (other buffer; reads of it were ordered by
        // the barrier above)
        if (kt + 1 < nt) { issueKV(kt + 1); CP_COMMIT(); }

        const uint32_t stU = smb + SM_ST0 + (kt & 1) * STG_B;
        const uint32_t kBaseH = stU + ST_KH + kFragOff;
        const uint32_t kBaseL = stU + ST_KL + kFragOff;
        const uint32_t vBaseH = stU + ST_VTH + vFragOff;
        const uint32_t vBaseL = stU + ST_VTL + vFragOff;
        const int k0 = kt << 5;

        // ---- S = Q K^T (bf16x3, ldmatrix fragments) ----
        float S1[4][4], S2[4][4];
#pragma unroll
        for (int j = 0; j < 4; j++)
#pragma unroll
            for (int i = 0; i < 4; i++) { S1[j][i] = 0.f; S2[j][i] = 0.f; }

#pragma unroll
        for (int ks = 0; ks < 16; ks++) {
            const uint32_t kb = (uint32_t)(ks * 32);
            uint32_t ah[4], al[4];
            LDMATRIX_X4(ah[0], ah[1], ah[2], ah[3], qFragH + kb);
            LDMATRIX_X4(al[0], al[1], al[2], al[3], qFragL + kb);
            uint32_t bh[4][2], bl[4][2];
#pragma unroll
            for (int jj = 0; jj < 2; jj++) {
                uint32_t q0, q1, q2, q3;
                LDMATRIX_X4(q0, q1, q2, q3, kBaseH + jj * 8448 + kb);
                bh[2 * jj][0] = q0; bh[2 * jj][1] = q1;
                bh[2 * jj + 1][0] = q2; bh[2 * jj + 1][1] = q3;
                LDMATRIX_X4(q0, q1, q2, q3, kBaseL + jj * 8448 + kb);
                bl[2 * jj][0] = q0; bl[2 * jj][1] = q1;
                bl[2 * jj + 1][0] = q2; bl[2 * jj + 1][1] = q3;
            }
#pragma unroll
            for (int j = 0; j < 4; j++) {
                mma_bf16(S1[j][0], S1[j][1], S1[j][2], S1[j][3],
                         ah[0], ah[1], ah[2], ah[3], bh[j][0], bh[j][1]);
                mma_bf16(S2[j][0], S2[j][1], S2[j][2], S2[j][3],
                         ah[0], ah[1], ah[2], ah[3], bl[j][0], bl[j][1]);
                mma_bf16(S2[j][0], S2[j][1], S2[j][2], S2[j][3],
                         al[0], al[1], al[2], al[3], bh[j][0], bh[j][1]);
            }
        }

        // ---- online softmax ----
        float p[4][4];
        const bool needmask = (k0 + 31) > (q0 + w * 16);
        float tm0 = -1e30f, tm1 = -1e30f;
#pragma unroll
        for (int j = 0; j < 4; j++) {
#pragma unroll
            for (int i = 0; i < 4; i++) {
                float s = S1[j][i] + S2[j][i];
                if (needmask) {
                    const int col = k0 + 8 * j + 2 * tig + (i & 1);
                    const int row = q0 + w * 16 + gid + ((i >= 2) ? 8 : 0);
                    if (col > row) s = -1e30f;
                }
                p[j][i] = s;
                if (i < 2) tm0 = fmaxf(tm0, s); else tm1 = fmaxf(tm1, s);
            }
        }
        tm0 = fmaxf(tm0, __shfl_xor_sync(0xffffffffu, tm0, 1));
        tm0 = fmaxf(tm0, __shfl_xor_sync(0xffffffffu, tm0, 2));
        tm1 = fmaxf(tm1, __shfl_xor_sync(0xffffffffu, tm1, 1));
        tm1 = fmaxf(tm1, __shfl_xor_sync(0xffffffffu, tm1, 2));

        const float mn0 = fmaxf(m0, tm0), mn1 = fmaxf(m1, tm1);
        const float a0 = __expf(m0 - mn0), a1 = __expf(m1 - mn1);

        float sum0 = 0.f, sum1 = 0.f;
#pragma unroll
        for (int j = 0; j < 4; j++) {
            p[j][0] = __expf(p[j][0] - mn0); sum0 += p[j][0];
            p[j][1] = __expf(p[j][1] - mn0); sum0 += p[j][1];
            p[j][2] = __expf(p[j][2] - mn1); sum1 += p[j][2];
            p[j][3] = __expf(p[j][3] - mn1); sum1 += p[j][3];
        }
        sum0 += __shfl_xor_sync(0xffffffffu, sum0, 1);
        sum0 += __shfl_xor_sync(0xffffffffu, sum0, 2);
        sum1 += __shfl_xor_sync(0xffffffffu, sum1, 1);
        sum1 += __shfl_xor_sync(0xffffffffu, sum1, 2);

        l0 = l0 * a0 + sum0;  m0 = mn0;
        l1 = l1 * a1 + sum1;  m1 = mn1;

#pragma unroll
        for (int n = 0; n < 32; n++) {
            O[n][0] *= a0; O[n][1] *= a0;
            O[n][2] *= a1; O[n][3] *= a1;
        }

        // ---- P fragments (hi/lo split, direct from registers) ----
        uint32_t ph[2][4], pl[2][4];
#pragma unroll
        for (int kk = 0; kk < 2; kk++) {
#pragma unroll
            for (int q = 0; q < 4; q++) {
                const int j = 2 * kk + (q >> 1);
                const int i0 = (q & 1) * 2;
                __nv_bfloat16 h0, lo0, h1, lo1;
                split_bf16(p[j][i0], h0, lo0);
                split_bf16(p[j][i0 + 1], h1, lo1);
                ph[kk][q] = pack2(h0, h1);
                pl[kk][q] = pack2(lo0, lo1);
            }
        }

        // ---- O += P V (bf16x3, ldmatrix fragments, n-pairs) ----
#pragma unroll
        for (int n0 = 0; n0 < 16; n0++) {
#pragma unroll
            for (int kk = 0; kk < 2; kk++) {
                uint32_t vh[4], vl[4];
                LDMATRIX_X4(vh[0], vh[1], vh[2], vh[3],
                            vBaseH + n0 * 1280 + kk * 32);
                LDMATRIX_X4(vl[0], vl[1], vl[2], vl[3],
                            vBaseL + n0 * 1280 + kk * 32);
                float* dA = O[2 * n0];
                float* dB = O[2 * n0 + 1];
                mma_bf16(dA[0], dA[1], dA[2], dA[3],
                         ph[kk][0], ph[kk][1], ph[kk][2], ph[kk][3],
                         vh[0], vh[1]);
                mma_bf16(dA[0], dA[1], dA[2], dA[3],
                         ph[kk][0], ph[kk][1], ph[kk][2], ph[kk][3],
                         vl[0], vl[1]);
                mma_bf16(dA[0], dA[1], dA[2], dA[3],
                         pl[kk][0], pl[kk][1], pl[kk][2], pl[kk][3],
                         vh[0], vh[1]);
                mma_bf16(dB[0], dB[1], dB[2], dB[3],
                         ph[kk][0], ph[kk][1], ph[kk][2], ph[kk][3],
                         vh[2], vh[3]);
                mma_bf16(dB[0], dB[1], dB[2], dB[3],
                         ph[kk][0], ph[kk][1], ph[kk][2], ph[kk][3],
                         vl[2], vl[3]);
                mma_bf16(dB[0], dB[1], dB[2], dB[3],
                         pl[kk][0], pl[kk][1], pl[kk][2], pl[kk][3],
                         vh[2], vh[3]);
            }
        }
        // no trailing barrier: next iteration's top barrier provides ordering.
    }

    // ---- epilogue: O/l -> bf16 hi/lo -> global ----
    const float inv0 = 1.f / l0, inv1 = 1.f / l1;
    const size_t ro0 = (size_t)(b * S_ + q0 + w * 16 + gid) * (NH_ * HD_)
                       + h * HD_;
    const size_t ro1 = ro0 + (size_t)8 * (NH_ * HD_);
#pragma unroll
    for (int n = 0; n < 32; n++) {
        const int col = 8 * n + 2 * tig;
        __nv_bfloat16 h0, lo0, h1, lo1;
        split_bf16(O[n][0] * inv0, h0, lo0);
        split_bf16(O[n][1] * inv0, h1, lo1);
        *(uint32_t*)(Ohi + ro0 + col) = pack2(h0, h1);
        *(uint32_t*)(Olo + ro0 + col) = pack2(lo0, lo1);
        split_bf16(O[n][2] * inv1, h0, lo0);
        split_bf16(O[n][3] * inv1, h1, lo1);
        *(uint32_t*)(Ohi + ro1 + col) = pack2(h0, h1);
        *(uint32_t*)(Olo + ro1 + col) = pack2(lo0, lo1);
    }
}

// ---------------------------------------------------------------------------
// Launch
// ---------------------------------------------------------------------------
extern "C" void kernel_launch(void* const* d_in, const int* in_sizes, int n_in,
                              void* d_out, int out_size)
{
    const float* hidden    = (const float*)d_in[0];
    const int*   positions = (const int*)  d_in[1];
    const float* w_qkv     = (const float*)d_in[2];
    const float* w_o       = (const float*)d_in[3];
    const float* q_norm_w  = (const float*)d_in[4];
    const float* k_norm_w  = (const float*)d_in[5];
    float*       out       = (float*)d_out;

    float *qkv, *V;
    __nv_bfloat16 *qh, *ql, *kh, *kl, *vth, *vtl;
    __nv_bfloat16 *hidH, *hidL, *attH, *attL, *wqkH, *wqkL, *woH, *woL;
    cudaGetSymbolAddress((void**)&qkv,  g_qkv);
    cudaGetSymbolAddress((void**)&V,    g_v);
    cudaGetSymbolAddress((void**)&qh,   g_qh);
    cudaGetSymbolAddress((void**)&ql,   g_ql);
    cudaGetSymbolAddress((void**)&kh,   g_kh);
    cudaGetSymbolAddress((void**)&kl,   g_kl);
    cudaGetSymbolAddress((void**)&vth,  g_vth);
    cudaGetSymbolAddress((void**)&vtl,  g_vtl);
    cudaGetSymbolAddress((void**)&hidH, g_hid_hi);
    cudaGetSymbolAddress((void**)&hidL, g_hid_lo);
    cudaGetSymbolAddress((void**)&attH, g_attn_hi);
    cudaGetSymbolAddress((void**)&attL, g_attn_lo);
    cudaGetSymbolAddress((void**)&wqkH, g_wqkT_hi);
    cudaGetSymbolAddress((void**)&wqkL, g_wqkT_lo);
    cudaGetSymbolAddress((void**)&woH,  g_woT_hi);
    cudaGetSymbolAddress((void**)&woL,  g_woT_lo);

    const int GEMM_SMEM = NSTAGE * STAGE_B;      // 81920
    cudaFuncSetAttribute(gemm_bf16x3_k,
        cudaFuncAttributeMaxDynamicSharedMemorySize, GEMM_SMEM);
    cudaFuncSetAttribute(attn_mma_k,
        cudaFuncAttributeMaxDynamicSharedMemorySize, ATTN_SMEM_TOTAL);

    // 0) operand preparation
    {
        const int n4 = (MROWS * HIDDEN_) / 4;
        split_k<<<(n4 + 255) / 256, 256>>>(hidden, hidH, hidL, n4);
    }
    transpose_split_k<<<dim3(QKV_N / 32, HIDDEN_ / 32), dim3(32, 8)>>>(
        w_qkv, wqkH, wqkL, HIDDEN_, QKV_N);
    transpose_split_k<<<dim3((NH_ * HD_) / 32, HIDDEN_ / 32), dim3(32, 8)>>>(
        w_o, woH, woL, HIDDEN_, NH_ * HD_);

    // 1) QKV projection
    gemm_bf16x3_k<<<dim3(QKV_N / 128, MROWS / 128), 256, GEMM_SMEM>>>(
        hidH, hidL, wqkH, wqkL, qkv, MROWS, QKV_N, HIDDEN_);

    // 2) rmsnorm + rope -> Q/K bf16 hi/lo, V fp32
    qkv_post_k<<<dim3(12, S_, B_), 256>>>(
        qkv, positions, q_norm_w, k_norm_w, qh, ql, kh, kl, V);

    // 2b) V^T split: [s][d] fp32 -> [d][s] bf16 hi/lo, per (b, kvh) slice
    for (int sl = 0; sl < B_ * NKV_; sl++) {
        transpose_split_k<<<dim3(HD_ / 32, S_ / 32), dim3(32, 8)>>>(
            V + (size_t)sl * S_ * HD_,
            vth + (size_t)sl * HD_ * S_,
            vtl + (size_t)sl * HD_ * S_, S_, HD_);
    }

    // 3) causal attention on tensor cores (ldmatrix, 1 barrier/tile)
    attn_mma_k<<<dim3(S_ / 64, NH_, B_), 128, ATTN_SMEM_TOTAL>>>(
        qh, ql, kh, kl, vth, vtl, attH, attL);

    // 4) output projection
    gemm_bf16x3_k<<<dim3((NH_ * HD_) / 128, MROWS / 128), 256, GEMM_SMEM>>>(
        attH, attL, woH, woL, out, MROWS, NH_ * HD_, HIDDEN_);
}

// round 13
// speedup vs baseline: 1.5021x; 1.5021x over previous
#include <cuda_runtime.h>
#include <cuda_bf16.h>
#include <math.h>
#include <stdint.h>

// ---------------------------------------------------------------------------
// Problem constants
// ---------------------------------------------------------------------------
#define B_      2
#define S_      2048
#define HIDDEN_ 2048
#define NH_     8
#define NKV_    2
#define HD_     256
#define QKV_N   3072          // (8 + 2*2) * 256
#define MROWS   (B_ * S_)     // 4096

// ---------------------------------------------------------------------------
// Scratch (device globals; no allocation allowed)
// ---------------------------------------------------------------------------
__device__ float         g_qkv    [(size_t)MROWS * QKV_N];
__device__ float         g_v      [(size_t)B_ * NKV_ * S_ * HD_];   // fp32 V
__device__ __nv_bfloat16 g_qh     [(size_t)B_ * NH_  * S_ * HD_];
__device__ __nv_bfloat16 g_ql     [(size_t)B_ * NH_  * S_ * HD_];
__device__ __nv_bfloat16 g_kh     [(size_t)B_ * NKV_ * S_ * HD_];
__device__ __nv_bfloat16 g_kl     [(size_t)B_ * NKV_ * S_ * HD_];
__device__ __nv_bfloat16 g_vth    [(size_t)B_ * NKV_ * HD_ * S_];   // V^T [d][s]
__device__ __nv_bfloat16 g_vtl    [(size_t)B_ * NKV_ * HD_ * S_];
__device__ __nv_bfloat16 g_hid_hi [(size_t)MROWS * HIDDEN_];
__device__ __nv_bfloat16 g_hid_lo [(size_t)MROWS * HIDDEN_];
__device__ __nv_bfloat16 g_attn_hi[(size_t)MROWS * (NH_ * HD_)];
__device__ __nv_bfloat16 g_attn_lo[(size_t)MROWS * (NH_ * HD_)];
__device__ __nv_bfloat16 g_wqkT_hi[(size_t)QKV_N * HIDDEN_];
__device__ __nv_bfloat16 g_wqkT_lo[(size_t)QKV_N * HIDDEN_];
__device__ __nv_bfloat16 g_woT_hi [(size_t)HIDDEN_ * (NH_ * HD_)];
__device__ __nv_bfloat16 g_woT_lo [(size_t)HIDDEN_ * (NH_ * HD_)];

// ---------------------------------------------------------------------------
// Helpers
// ---------------------------------------------------------------------------
__device__ __forceinline__ uint32_t smem_u32(const void* p) {
    uint32_t a;
    asm("{ .reg .u64 t; cvta.to.shared.u64 t, %1; cvt.u32.u64 %0, t; }"
        : "=r"(a) : "l"(p));
    return a;
}

#define CP_ASYNC16(sm, gp) \
    asm volatile("cp.async.cg.shared.global [%0], [%1], 16;" \
        :: "r"(sm), "l"(gp) : "memory")
#define CP_COMMIT() asm volatile("cp.async.commit_group;" ::: "memory")
#define CP_WAIT0()  asm volatile("cp.async.wait_group 0;"  ::: "memory")
#define CP_WAIT1()  asm volatile("cp.async.wait_group 1;"  ::: "memory")

#define LDMATRIX_X4(r0, r1, r2, r3, addr) \
    asm volatile("ldmatrix.sync.aligned.m8n8.x4.shared.b16 {%0,%1,%2,%3}, [%4];" \
        : "=r"(r0), "=r"(r1), "=r"(r2), "=r"(r3) : "r"(addr))

__device__ __forceinline__ void mma_bf16(
    float& d0, float& d1, float& d2, float& d3,
    uint32_t a0, uint32_t a1, uint32_t a2, uint32_t a3,
    uint32_t b0, uint32_t b1)
{
    asm volatile(
        "mma.sync.aligned.m16n8k16.row.col.f32.bf16.bf16.f32 "
        "{%0,%1,%2,%3}, {%4,%5,%6,%7}, {%8,%9}, {%0,%1,%2,%3};"
        : "+f"(d0), "+f"(d1), "+f"(d2), "+f"(d3)
        : "r"(a0), "r"(a1), "r"(a2), "r"(a3), "r"(b0), "r"(b1));
}

__device__ __forceinline__ void split_bf16(float x, __nv_bfloat16& hi,
                                           __nv_bfloat16& lo) {
    hi = __float2bfloat16_rn(x);
    lo = __float2bfloat16_rn(x - __bfloat162float(hi));
}
__device__ __forceinline__ uint32_t pack2(__nv_bfloat16 lo, __nv_bfloat16 hi) {
    __nv_bfloat162 r;
    r.x = lo; r.y = hi;
    return *(uint32_t*)&r;
}

// ---------------------------------------------------------------------------
// Elementwise fp32 -> (hi, lo) bf16 split. n4 = element count / 4.
// ---------------------------------------------------------------------------
__global__ __launch_bounds__(256) void split_k(
    const float* __restrict__ in, __nv_bfloat16* __restrict__ hi,
    __nv_bfloat16* __restrict__ lo, int n4)
{
    int i = blockIdx.x * 256 + threadIdx.x;
    if (i >= n4) return;
    float4 v = ((const float4*)in)[i];
    __nv_bfloat16 h[4], l[4];
    split_bf16(v.x, h[0], l[0]);
    split_bf16(v.y, h[1], l[1]);
    split_bf16(v.z, h[2], l[2]);
    split_bf16(v.w, h[3], l[3]);
    ((uint2*)hi)[i] = *(uint2*)h;
    ((uint2*)lo)[i] = *(uint2*)l;
}

// ---------------------------------------------------------------------------
// Transpose + split: outHi/outLo[n][k] = split(in[k][n]); in is R x C.
// ---------------------------------------------------------------------------
__global__ __launch_bounds__(256) void transpose_split_k(
    const float* __restrict__ in, __nv_bfloat16* __restrict__ outHi,
    __nv_bfloat16* __restrict__ outLo, int R, int C)
{
    __shared__ float tile[32][33];
    const int tx = threadIdx.x, ty = threadIdx.y;
    const int c0 = blockIdx.x * 32, r0 = blockIdx.y * 32;
#pragma unroll
    for (int i = ty; i < 32; i += 8)
        tile[i][tx] = in[(size_t)(r0 + i) * C + c0 + tx];
    __syncthreads();
#pragma unroll
    for (int i = ty; i < 32; i += 8) {
        __nv_bfloat16 h, l;
        split_bf16(tile[tx][i], h, l);
        outHi[(size_t)(c0 + i) * R + r0 + tx] = h;
        outLo[(size_t)(c0 + i) * R + r0 + tx] = l;
    }
}

// ---------------------------------------------------------------------------
// bf16x3 GEMM — ROUND-10 VERSION VERBATIM (best measured: 474 us QKV).
// 8 warps, warp tile 64x32, BK=32, ldmatrix, NSTAGE=2 (2 CTAs/SM),
// WAIT1 + issue-after-compute + two barriers per chunk.
// ---------------------------------------------------------------------------
#define ASTRIDE 40
#define TILE_B  (128 * ASTRIDE * 2)        // 10240 bytes
#define STAGE_B (4 * TILE_B)               // 40960 bytes
#define NSTAGE  2

__global__ __launch_bounds__(256, 2) void gemm_bf16x3_k(
    const __nv_bfloat16* __restrict__ Ahi, const __nv_bfloat16* __restrict__ Alo,
    const __nv_bfloat16* __restrict__ Bhi, const __nv_bfloat16* __restrict__ Blo,
    float* __restrict__ C, int M, int N, int K)
{
    extern __shared__ char dsm[];
    const int t    = threadIdx.x;
    const int lane = t & 31, w = t >> 5;
    const int gid  = lane >> 2, tig = lane & 3;
    const int wm   = (w >> 2) * 64;
    const int wn   = (w & 3) * 32;
    const int brow = blockIdx.y * 128;
    const int bcol = blockIdx.x * 128;

    const uint32_t smBase = smem_u32(dsm);

    const int lm = lane >> 3;              // matrix index 0..3
    const int lr = lane & 7;
    const uint32_t aFragOff =
        (uint32_t)((wm + (lm & 1) * 8 + lr) * 80 + (lm >> 1) * 16);
    const uint32_t bFragOff =
        (uint32_t)((wn + (lm >> 1) * 8 + lr) * 80 + (lm & 1) * 16);

    float acc[16][4];
#pragma unroll
    for (int i = 0; i < 16; i++)
#pragma unroll
        for (int j = 0; j < 4; j++) acc[i][j] = 0.f;

    const int nk = K >> 5;

    auto issue = [&](int s, int kt) {
        const uint32_t st = smBase + s * STAGE_B;
        const int k0 = kt << 5;
        const __nv_bfloat16* srcs[4] = { Ahi, Alo, Bhi, Blo };
        const int rb[4] = { brow, brow, bcol, bcol };
#pragma unroll
        for (int m = 0; m < 4; m++) {
            const uint32_t dst = st + m * TILE_B;
#pragma unroll
            for (int i = 0; i < 2; i++) {
                const int j = i * 256 + t;
                const int r = j >> 2, kq = j & 3;
                CP_ASYNC16(dst + (uint32_t)(r * ASTRIDE + kq * 8) * 2,
                           srcs[m] + (size_t)(rb[m] + r) * K + k0 + kq * 8);
            }
        }
    };

    issue(0, 0); CP_COMMIT();
    issue(1, 1); CP_COMMIT();

    for (int kt = 0; kt < nk; kt++) {
        CP_WAIT1();
        __syncthreads();

        const int buf = kt & 1;
        const uint32_t stBase = smBase + buf * STAGE_B;
        const uint32_t aH = stBase + aFragOff;
        const uint32_t aL = aH + TILE_B;
        const uint32_t bH = stBase + 2 * TILE_B + bFragOff;
        const uint32_t bL = bH + TILE_B;

#pragma unroll
        for (int ks = 0; ks < 2; ks++) {
            const uint32_t kb = (uint32_t)(ks * 32);
            uint32_t ah[4][4], al[4][4];
#pragma unroll
            for (int mt = 0; mt < 4; mt++) {
                LDMATRIX_X4(ah[mt][0], ah[mt][1], ah[mt][2], ah[mt][3],
                            aH + mt * 1280 + kb);
                LDMATRIX_X4(al[mt][0], al[mt][1], al[mt][2], al[mt][3],
                            aL + mt * 1280 + kb);
            }
            uint32_t bh[4][2], bl[4][2];
#pragma unroll
            for (int jj = 0; jj < 2; jj++) {
                uint32_t q0, q1, q2, q3;
                LDMATRIX_X4(q0, q1, q2, q3, bH + jj * 1280 + kb);
                bh[2 * jj][0] = q0; bh[2 * jj][1] = q1;
                bh[2 * jj + 1][0] = q2; bh[2 * jj + 1][1] = q3;
                LDMATRIX_X4(q0, q1, q2, q3, bL + jj * 1280 + kb);
                bl[2 * jj][0] = q0; bl[2 * jj][1] = q1;
                bl[2 * jj + 1][0] = q2; bl[2 * jj + 1][1] = q3;
            }
#pragma unroll
            for (int nt = 0; nt < 4; nt++) {
#pragma unroll
                for (int mt = 0; mt < 4; mt++) {
                    float* d = acc[nt * 4 + mt];
                    mma_bf16(d[0], d[1], d[2], d[3],
                             ah[mt][0], ah[mt][1], ah[mt][2], ah[mt][3],
                             bh[nt][0], bh[nt][1]);
                    mma_bf16(d[0], d[1], d[2], d[3],
                             ah[mt][0], ah[mt][1], ah[mt][2], ah[mt][3],
                             bl[nt][0], bl[nt][1]);
                    mma_bf16(d[0], d[1], d[2], d[3],
                             al[mt][0], al[mt][1], al[mt][2], al[mt][3],
                             bh[nt][0], bh[nt][1]);
                }
            }
        }
        __syncthreads();                   // required: NSTAGE=2 reuses buf
        if (kt + 2 < nk) issue(buf, kt + 2);
        CP_COMMIT();
    }

#pragma unroll
    for (int nt = 0; nt < 4; nt++) {
#pragma unroll
        for (int mt = 0; mt < 4; mt++) {
            const float* d = acc[nt * 4 + mt];
            const int r0 = brow + wm + mt * 16 + gid;
            const int c0 = bcol + wn + nt * 8 + 2 * tig;
            *(float2*)&C[(size_t)r0 * N + c0]       = make_float2(d[0], d[1]);
            *(float2*)&C[(size_t)(r0 + 8) * N + c0] = make_float2(d[2], d[3]);
        }
    }
}

// ---------------------------------------------------------------------------
// Fused per-head RMSNorm (+ RoPE for q/k). Emits bf16 hi/lo for Q and K,
// fp32 for V (V^T split happens in transpose_split_k).
// ---------------------------------------------------------------------------
__global__ __launch_bounds__(256) void qkv_post_k(
    const float* __restrict__ qkv, const int* __restrict__ positions,
    const float* __restrict__ qw, const float* __restrict__ kw,
    __nv_bfloat16* __restrict__ QhO, __nv_bfloat16* __restrict__ QlO,
    __nv_bfloat16* __restrict__ KhO, __nv_bfloat16* __restrict__ KlO,
    float* __restrict__ V)
{
    const int h   = blockIdx.x;   // 0..11
    const int s   = blockIdx.y;
    const int b   = blockIdx.z;
    const int tid = threadIdx.x;  // 0..255

    __shared__ float red[8];
    __shared__ float sy[256];

    const float* row = qkv + (size_t)(b * S_ + s) * QKV_N;

    int off;
    float w = 1.0f;
    if (h < 8)       { off = h * 256;                w = qw[tid]; }
    else if (h < 10) { off = 2048 + (h - 8) * 256;   w = kw[tid]; }
    else             { off = 2560 + (h - 10) * 256; }

    float x = row[off + tid];
    float v = x * x;
#pragma unroll
    for (int o = 16; o > 0; o >>= 1) v += __shfl_xor_sync(0xffffffffu, v, o);
    if ((tid & 31) == 0) red[tid >> 5] = v;
    __syncthreads();
    float ss = 0.f;
#pragma unroll
    for (int i = 0; i < 8; i++) ss += red[i];

    float y = x * rsqrtf(ss * (1.0f / 256.0f) + 1e-6f) * w;

    if (h >= 10) {
        V[((size_t)(b * NKV_ + (h - 10)) * S_ + s) * HD_ + tid] = y;
        return;
    }

    sy[tid] = y;
    __syncthreads();

    if (tid < 128) {
        float invf = powf(1000000.0f, -(float)tid * (1.0f / 128.0f));
        float f    = (float)positions[b * S_ + s] * invf;
        float si, co;
        sincosf(f, &si, &co);
        float x1 = sy[tid];
        float x2 = sy[tid + 128];
        float o1 = x1 * co - x2 * si;
        float o2 = x2 * co + x1 * si;
        __nv_bfloat16 h1, l1, h2, l2;
        split_bf16(o1, h1, l1);
        split_bf16(o2, h2, l2);
        if (h < 8) {
            size_t base = ((size_t)(b * NH_ + h) * S_ + s) * HD_;
            QhO[base + tid] = h1;       QlO[base + tid] = l1;
            QhO[base + tid + 128] = h2; QlO[base + tid + 128] = l2;
        } else {
            size_t base = ((size_t)(b * NKV_ + (h - 8)) * S_ + s) * HD_;
            KhO[base + tid] = h1;       KlO[base + tid] = l1;
            KhO[base + tid + 128] = h2; KlO[base + tid + 128] = l2;
        }
    }
}

// ---------------------------------------------------------------------------
// Flash attention on HMMA with bf16x3 emulation.
// ROUND-10 pipeline (issue(kt+1)->COMMIT->WAIT1->sync->compute->sync,
// double-buffered BK=32 KV, 217 KB smem, 1 CTA/SM, heavy-first)
// + ldmatrix fragment loads (round-11-verified mappings).
// ---------------------------------------------------------------------------
#define QROWB   528                     // bytes per Q/K smem row (264 bf16)
#define VROWB   80                      // bytes per Vt smem row (40 bf16)
#define SM_QH   0
#define SM_QL   33792                   // 64*528
#define SM_ST0  67584
#define STG_B   74752                   // K(16896*2) + Vt(20480*2)
#define ST_KH   0
#define ST_KL   16896
#define ST_VTH  33792
#define ST_VTL  54272
#define ATTN_SMEM_TOTAL (SM_ST0 + 2 * STG_B)   // 217088

__global__ __launch_bounds__(128, 1) void attn_mma_k(
    const __nv_bfloat16* __restrict__ Qh, const __nv_bfloat16* __restrict__ Ql,
    const __nv_bfloat16* __restrict__ Kh, const __nv_bfloat16* __restrict__ Kl,
    const __nv_bfloat16* __restrict__ Vth, const __nv_bfloat16* __restrict__ Vtl,
    __nv_bfloat16* __restrict__ Ohi, __nv_bfloat16* __restrict__ Olo)
{
    extern __shared__ char dsm[];
    const int t    = threadIdx.x;
    const int lane = t & 31, w = t >> 5;
    const int gid  = lane >> 2, tig = lane & 3;
    const int h    = blockIdx.y, b = blockIdx.z;
    const int qt   = gridDim.x - 1 - blockIdx.x;   // heavy tiles first
    const int q0   = qt * 64;
    const int kvh  = h >> 2;
    const uint32_t smb = smem_u32(dsm);

    const __nv_bfloat16* qhg = Qh + ((size_t)(b * NH_ + h) * S_ + q0) * HD_;
    const __nv_bfloat16* qlg = Ql + ((size_t)(b * NH_ + h) * S_ + q0) * HD_;
    const __nv_bfloat16* khg = Kh + (size_t)(b * NKV_ + kvh) * S_ * HD_;
    const __nv_bfloat16* klg = Kl + (size_t)(b * NKV_ + kvh) * S_ * HD_;
    const __nv_bfloat16* vhg = Vth + (size_t)(b * NKV_ + kvh) * HD_ * S_;
    const __nv_bfloat16* vlg = Vtl + (size_t)(b * NKV_ + kvh) * HD_ * S_;

    // ---- stage Q (hi+lo): 64 rows x 256 bf16 each ----
#pragma unroll
    for (int i = 0; i < 16; i++) {
        const int j = i * 128 + t;             // 0..2047
        const int r = j >> 5, c = j & 31;
        CP_ASYNC16(smb + SM_QH + r * QROWB + c * 16, qhg + (size_t)r * HD_ + c * 8);
        CP_ASYNC16(smb + SM_QL + r * QROWB + c * 16, qlg + (size_t)r * HD_ + c * 8);
    }

    const int nt = qt * 2 + 2;                // K-tiles of 32

    auto issueKV = [&](int kt) {
        const uint32_t st = smb + SM_ST0 + (kt & 1) * STG_B;
        const int k0 = kt << 5;
#pragma unroll
        for (int i = 0; i < 8; i++) {
            const int j = i * 128 + t;         // 0..1023
            const int r = j >> 5, c = j & 31;  // K: row, 8-elt chunk
            CP_ASYNC16(st + ST_KH + r * QROWB + c * 16,
                       khg + (size_t)(k0 + r) * HD_ + c * 8);
            CP_ASYNC16(st + ST_KL + r * QROWB + c * 16,
                       klg + (size_t)(k0 + r) * HD_ + c * 8);
            const int vr = j >> 2, vc = j & 3; // Vt: row d, 8-elt chunk
            CP_ASYNC16(st + ST_VTH + vr * VROWB + vc * 16,
                       vhg + (size_t)vr * S_ + k0 + vc * 8);
            CP_ASYNC16(st + ST_VTL + vr * VROWB + vc * 16,
                       vlg + (size_t)vr * S_ + k0 + vc * 8);
        }
    };

    issueKV(0); CP_COMMIT();

    float O[32][4];
#pragma unroll
    for (int n = 0; n < 32; n++)
#pragma unroll
        for (int i = 0; i < 4; i++) O[n][i] = 0.f;
    float m0 = -1e30f, m1 = -1e30f, l0 = 0.f, l1 = 0.f;

    // ldmatrix per-lane offsets (round-11-verified)
    const int lm = lane >> 3, lr = lane & 7;
    const uint32_t qFragH = smb + SM_QH +
        (uint32_t)((w * 16 + (lm & 1) * 8 + lr) * QROWB + (lm >> 1) * 16);
    const uint32_t qFragL = qFragH + (SM_QL - SM_QH);
    const uint32_t kFragOff =
        (uint32_t)(((lm >> 1) * 8 + lr) * QROWB + (lm & 1) * 16);
    const uint32_t vFragOff =
        (uint32_t)(((lm >> 1) * 8 + lr) * VROWB + (lm & 1) * 16);

    for (int kt = 0; kt < nt; kt++) {
        const bool more = (kt + 1 < nt);
        if (more) { issueKV(kt + 1); CP_COMMIT(); }
        if (more) CP_WAIT1(); else CP_WAIT0();
        __syncthreads();

        const uint32_t stU = smb + SM_ST0 + (kt & 1) * STG_B;
        const uint32_t kBaseH = stU + ST_KH + kFragOff;
        const uint32_t kBaseL = stU + ST_KL + kFragOff;
        const uint32_t vBaseH = stU + ST_VTH + vFragOff;
        const uint32_t vBaseL = stU + ST_VTL + vFragOff;
        const int k0 = kt << 5;

        // ---- S = Q K^T (bf16x3, ldmatrix fragments) ----
        float S1[4][4], S2[4][4];
#pragma unroll
        for (int j = 0; j < 4; j++)
#pragma unroll
            for (int i = 0; i < 4; i++) { S1[j][i] = 0.f; S2[j][i] = 0.f; }

#pragma unroll
        for (int ks = 0; ks < 16; ks++) {
            const uint32_t kb = (uint32_t)(ks * 32);
            uint32_t ah[4], al[4];
            LDMATRIX_X4(ah[0], ah[1], ah[2], ah[3], qFragH + kb);
            LDMATRIX_X4(al[0], al[1], al[2], al[3], qFragL + kb);
            uint32_t bh[4][2], bl[4][2];
#pragma unroll
            for (int jj = 0; jj < 2; jj++) {
                uint32_t q0, q1, q2, q3;
                LDMATRIX_X4(q0, q1, q2, q3, kBaseH + jj * 8448 + kb);
                bh[2 * jj][0] = q0; bh[2 * jj][1] = q1;
                bh[2 * jj + 1][0] = q2; bh[2 * jj + 1][1] = q3;
                LDMATRIX_X4(q0, q1, q2, q3, kBaseL + jj * 8448 + kb);
                bl[2 * jj][0] = q0; bl[2 * jj][1] = q1;
                bl[2 * jj + 1][0] = q2; bl[2 * jj + 1][1] = q3;
            }
#pragma unroll
            for (int j = 0; j < 4; j++) {
                mma_bf16(S1[j][0], S1[j][1], S1[j][2], S1[j][3],
                         ah[0], ah[1], ah[2], ah[3], bh[j][0], bh[j][1]);
                mma_bf16(S2[j][0], S2[j][1], S2[j][2], S2[j][3],
                         ah[0], ah[1], ah[2], ah[3], bl[j][0], bl[j][1]);
                mma_bf16(S2[j][0], S2[j][1], S2[j][2], S2[j][3],
                         al[0], al[1], al[2], al[3], bh[j][0], bh[j][1]);
            }
        }

        // ---- online softmax ----
        float p[4][4];
        const bool needmask = (k0 + 31) > (q0 + w * 16);
        float tm0 = -1e30f, tm1 = -1e30f;
#pragma unroll
        for (int j = 0; j < 4; j++) {
#pragma unroll
            for (int i = 0; i < 4; i++) {
                float s = S1[j][i] + S2[j][i];
                if (needmask) {
                    const int col = k0 + 8 * j + 2 * tig + (i & 1);
                    const int row = q0 + w * 16 + gid + ((i >= 2) ? 8 : 0);
                    if (col > row) s = -1e30f;
                }
                p[j][i] = s;
                if (i < 2) tm0 = fmaxf(tm0, s); else tm1 = fmaxf(tm1, s);
            }
        }
        tm0 = fmaxf(tm0, __shfl_xor_sync(0xffffffffu, tm0, 1));
        tm0 = fmaxf(tm0, __shfl_xor_sync(0xffffffffu, tm0, 2));
        tm1 = fmaxf(tm1, __shfl_xor_sync(0xffffffffu, tm1, 1));
        tm1 = fmaxf(tm1, __shfl_xor_sync(0xffffffffu, tm1, 2));

        const float mn0 = fmaxf(m0, tm0), mn1 = fmaxf(m1, tm1);
        const float a0 = __expf(m0 - mn0), a1 = __expf(m1 - mn1);

        float sum0 = 0.f, sum1 = 0.f;
#pragma unroll
        for (int j = 0; j < 4; j++) {
            p[j][0] = __expf(p[j][0] - mn0); sum0 += p[j][0];
            p[j][1] = __expf(p[j][1] - mn0); sum0 += p[j][1];
            p[j][2] = __expf(p[j][2] - mn1); sum1 += p[j][2];
            p[j][3] = __expf(p[j][3] - mn1); sum1 += p[j][3];
        }
        sum0 += __shfl_xor_sync(0xffffffffu, sum0, 1);
        sum0 += __shfl_xor_sync(0xffffffffu, sum0, 2);
        sum1 += __shfl_xor_sync(0xffffffffu, sum1, 1);
        sum1 += __shfl_xor_sync(0xffffffffu, sum1, 2);

        l0 = l0 * a0 + sum0;  m0 = mn0;
        l1 = l1 * a1 + sum1;  m1 = mn1;

#pragma unroll
        for (int n = 0; n < 32; n++) {
            O[n][0] *= a0; O[n][1] *= a0;
            O[n][2] *= a1; O[n][3] *= a1;
        }

        // ---- P fragments (hi/lo split, direct from registers) ----
        uint32_t ph[2][4], pl[2][4];
#pragma unroll
        for (int kk = 0; kk < 2; kk++) {
#pragma unroll
            for (int q = 0; q < 4; q++) {
                const int j = 2 * kk + (q >> 1);
                const int i0 = (q & 1) * 2;
                __nv_bfloat16 h0, lo0, h1, lo1;
                split_bf16(p[j][i0], h0, lo0);
                split_bf16(p[j][i0 + 1], h1, lo1);
                ph[kk][q] = pack2(h0, h1);
                pl[kk][q] = pack2(lo0, lo1);
            }
        }

        // ---- O += P V (bf16x3, ldmatrix fragments, n-pairs) ----
#pragma unroll
        for (int n0 = 0; n0 < 16; n0++) {
#pragma unroll
            for (int kk = 0; kk < 2; kk++) {
                uint32_t vh[4], vl[4];
                LDMATRIX_X4(vh[0], vh[1], vh[2], vh[3],
                            vBaseH + n0 * 1280 + kk * 32);
                LDMATRIX_X4(vl[0], vl[1], vl[2], vl[3],
                            vBaseL + n0 * 1280 + kk * 32);
                float* dA = O[2 * n0];
                float* dB = O[2 * n0 + 1];
                mma_bf16(dA[0], dA[1], dA[2], dA[3],
                         ph[kk][0], ph[kk][1], ph[kk][2], ph[kk][3],
                         vh[0], vh[1]);
                mma_bf16(dA[0], dA[1], dA[2], dA[3],
                         ph[kk][0], ph[kk][1], ph[kk][2], ph[kk][3],
                         vl[0], vl[1]);
                mma_bf16(dA[0], dA[1], dA[2], dA[3],
                         pl[kk][0], pl[kk][1], pl[kk][2], pl[kk][3],
                         vh[0], vh[1]);
                mma_bf16(dB[0], dB[1], dB[2], dB[3],
                         ph[kk][0], ph[kk][1], ph[kk][2], ph[kk][3],
                         vh[2], vh[3]);
                mma_bf16(dB[0], dB[1], dB[2], dB[3],
                         ph[kk][0], ph[kk][1], ph[kk][2], ph[kk][3],
                         vl[2], vl[3]);
                mma_bf16(dB[0], dB[1], dB[2], dB[3],
                         pl[kk][0], pl[kk][1], pl[kk][2], pl[kk][3],
                         vh[2], vh[3]);
            }
        }
        __syncthreads();
    }

    // ---- epilogue: O/l -> bf16 hi/lo -> global ----
    const float inv0 = 1.f / l0, inv1 = 1.f / l1;
    const size_t ro0 = (size_t)(b * S_ + q0 + w * 16 + gid) * (NH_ * HD_)
                       + h * HD_;
    const size_t ro1 = ro0 + (size_t)8 * (NH_ * HD_);
#pragma unroll
    for (int n = 0; n < 32; n++) {
        const int col = 8 * n + 2 * tig;
        __nv_bfloat16 h0, lo0, h1, lo1;
        split_bf16(O[n][0] * inv0, h0, lo0);
        split_bf16(O[n][1] * inv0, h1, lo1);
        *(uint32_t*)(Ohi + ro0 + col) = pack2(h0, h1);
        *(uint32_t*)(Olo + ro0 + col) = pack2(lo0, lo1);
        split_bf16(O[n][2] * inv1, h0, lo0);
        split_bf16(O[n][3] * inv1, h1, lo1);
        *(uint32_t*)(Ohi + ro1 + col) = pack2(h0, h1);
        *(uint32_t*)(Olo + ro1 + col) = pack2(lo0, lo1);
    }
}

// ---------------------------------------------------------------------------
// Launch
// ---------------------------------------------------------------------------
extern "C" void kernel_launch(void* const* d_in, const int* in_sizes, int n_in,
                              void* d_out, int out_size)
{
    const float* hidden    = (const float*)d_in[0];
    const int*   positions = (const int*)  d_in[1];
    const float* w_qkv     = (const float*)d_in[2];
    const float* w_o       = (const float*)d_in[3];
    const float* q_norm_w  = (const float*)d_in[4];
    const float* k_norm_w  = (const float*)d_in[5];
    float*       out       = (float*)d_out;

    float *qkv, *V;
    __nv_bfloat16 *qh, *ql, *kh, *kl, *vth, *vtl;
    __nv_bfloat16 *hidH, *hidL, *attH, *attL, *wqkH, *wqkL, *woH, *woL;
    cudaGetSymbolAddress((void**)&qkv,  g_qkv);
    cudaGetSymbolAddress((void**)&V,    g_v);
    cudaGetSymbolAddress((void**)&qh,   g_qh);
    cudaGetSymbolAddress((void**)&ql,   g_ql);
    cudaGetSymbolAddress((void**)&kh,   g_kh);
    cudaGetSymbolAddress((void**)&kl,   g_kl);
    cudaGetSymbolAddress((void**)&vth,  g_vth);
    cudaGetSymbolAddress((void**)&vtl,  g_vtl);
    cudaGetSymbolAddress((void**)&hidH, g_hid_hi);
    cudaGetSymbolAddress((void**)&hidL, g_hid_lo);
    cudaGetSymbolAddress((void**)&attH, g_attn_hi);
    cudaGetSymbolAddress((void**)&attL, g_attn_lo);
    cudaGetSymbolAddress((void**)&wqkH, g_wqkT_hi);
    cudaGetSymbolAddress((void**)&wqkL, g_wqkT_lo);
    cudaGetSymbolAddress((void**)&woH,  g_woT_hi);
    cudaGetSymbolAddress((void**)&woL,  g_woT_lo);

    const int GEMM_SMEM = NSTAGE * STAGE_B;      // 81920
    cudaFuncSetAttribute(gemm_bf16x3_k,
        cudaFuncAttributeMaxDynamicSharedMemorySize, GEMM_SMEM);
    cudaFuncSetAttribute(attn_mma_k,
        cudaFuncAttributeMaxDynamicSharedMemorySize, ATTN_SMEM_TOTAL);

    // 0) operand preparation
    {
        const int n4 = (MROWS * HIDDEN_) / 4;
        split_k<<<(n4 + 255) / 256, 256>>>(hidden, hidH, hidL, n4);
    }
    transpose_split_k<<<dim3(QKV_N / 32, HIDDEN_ / 32), dim3(32, 8)>>>(
        w_qkv, wqkH, wqkL, HIDDEN_, QKV_N);
    transpose_split_k<<<dim3((NH_ * HD_) / 32, HIDDEN_ / 32), dim3(32, 8)>>>(
        w_o, woH, woL, HIDDEN_, NH_ * HD_);

    // 1) QKV projection
    gemm_bf16x3_k<<<dim3(QKV_N / 128, MROWS / 128), 256, GEMM_SMEM>>>(
        hidH, hidL, wqkH, wqkL, qkv, MROWS, QKV_N, HIDDEN_);

    // 2) rmsnorm + rope -> Q/K bf16 hi/lo, V fp32
    qkv_post_k<<<dim3(12, S_, B_), 256>>>(
        qkv, positions, q_norm_w, k_norm_w, qh, ql, kh, kl, V);

    // 2b) V^T split: [s][d] fp32 -> [d][s] bf16 hi/lo, per (b, kvh) slice
    for (int sl = 0; sl < B_ * NKV_; sl++) {
        transpose_split_k<<<dim3(HD_ / 32, S_ / 32), dim3(32, 8)>>>(
            V + (size_t)sl * S_ * HD_,
            vth + (size_t)sl * HD_ * S_,
            vtl + (size_t)sl * HD_ * S_, S_, HD_);
    }

    // 3) causal attention (round-10 pipeline + ldmatrix fragments)
    attn_mma_k<<<dim3(S_ / 64, NH_, B_), 128, ATTN_SMEM_TOTAL>>>(
        qh, ql, kh, kl, vth, vtl, attH, attL);

    // 4) output projection
    gemm_bf16x3_k<<<dim3((NH_ * HD_) / 128, MROWS / 128), 256, GEMM_SMEM>>>(
        attH, attL, woH, woL, out, MROWS, NH_ * HD_, HIDDEN_);
}

// round 14
// speedup vs baseline: 1.5272x; 1.0167x over previous
#include <cuda_runtime.h>
#include <cuda_bf16.h>
#include <math.h>
#include <stdint.h>

// ---------------------------------------------------------------------------
// Problem constants
// ---------------------------------------------------------------------------
#define B_      2
#define S_      2048
#define HIDDEN_ 2048
#define NH_     8
#define NKV_    2
#define HD_     256
#define QKV_N   3072          // (8 + 2*2) * 256
#define MROWS   (B_ * S_)     // 4096

// ---------------------------------------------------------------------------
// Scratch (device globals; no allocation allowed)
// ---------------------------------------------------------------------------
__device__ float         g_qkv    [(size_t)MROWS * QKV_N];
__device__ float         g_v      [(size_t)B_ * NKV_ * S_ * HD_];   // fp32 V
__device__ __nv_bfloat16 g_qh     [(size_t)B_ * NH_  * S_ * HD_];
__device__ __nv_bfloat16 g_ql     [(size_t)B_ * NH_  * S_ * HD_];
__device__ __nv_bfloat16 g_kh     [(size_t)B_ * NKV_ * S_ * HD_];
__device__ __nv_bfloat16 g_kl     [(size_t)B_ * NKV_ * S_ * HD_];
__device__ __nv_bfloat16 g_vth    [(size_t)B_ * NKV_ * HD_ * S_];   // V^T [d][s]
__device__ __nv_bfloat16 g_vtl    [(size_t)B_ * NKV_ * HD_ * S_];
__device__ __nv_bfloat16 g_hid_hi [(size_t)MROWS * HIDDEN_];
__device__ __nv_bfloat16 g_hid_lo [(size_t)MROWS * HIDDEN_];
__device__ __nv_bfloat16 g_attn_hi[(size_t)MROWS * (NH_ * HD_)];
__device__ __nv_bfloat16 g_attn_lo[(size_t)MROWS * (NH_ * HD_)];
__device__ __nv_bfloat16 g_wqkT_hi[(size_t)QKV_N * HIDDEN_];
__device__ __nv_bfloat16 g_wqkT_lo[(size_t)QKV_N * HIDDEN_];
__device__ __nv_bfloat16 g_woT_hi [(size_t)HIDDEN_ * (NH_ * HD_)];
__device__ __nv_bfloat16 g_woT_lo [(size_t)HIDDEN_ * (NH_ * HD_)];

// ---------------------------------------------------------------------------
// Helpers
// ---------------------------------------------------------------------------
__device__ __forceinline__ uint32_t smem_u32(const void* p) {
    uint32_t a;
    asm("{ .reg .u64 t; cvta.to.shared.u64 t, %1; cvt.u32.u64 %0, t; }"
        : "=r"(a) : "l"(p));
    return a;
}

#define CP_ASYNC16(sm, gp) \
    asm volatile("cp.async.cg.shared.global [%0], [%1], 16;" \
        :: "r"(sm), "l"(gp) : "memory")
#define CP_COMMIT() asm volatile("cp.async.commit_group;" ::: "memory")
#define CP_WAIT0()  asm volatile("cp.async.wait_group 0;"  ::: "memory")
#define CP_WAIT1()  asm volatile("cp.async.wait_group 1;"  ::: "memory")

#define LDMATRIX_X4(r0, r1, r2, r3, addr) \
    asm volatile("ldmatrix.sync.aligned.m8n8.x4.shared.b16 {%0,%1,%2,%3}, [%4];" \
        : "=r"(r0), "=r"(r1), "=r"(r2), "=r"(r3) : "r"(addr))

__device__ __forceinline__ void mma_bf16(
    float& d0, float& d1, float& d2, float& d3,
    uint32_t a0, uint32_t a1, uint32_t a2, uint32_t a3,
    uint32_t b0, uint32_t b1)
{
    asm volatile(
        "mma.sync.aligned.m16n8k16.row.col.f32.bf16.bf16.f32 "
        "{%0,%1,%2,%3}, {%4,%5,%6,%7}, {%8,%9}, {%0,%1,%2,%3};"
        : "+f"(d0), "+f"(d1), "+f"(d2), "+f"(d3)
        : "r"(a0), "r"(a1), "r"(a2), "r"(a3), "r"(b0), "r"(b1));
}

__device__ __forceinline__ void split_bf16(float x, __nv_bfloat16& hi,
                                           __nv_bfloat16& lo) {
    hi = __float2bfloat16_rn(x);
    lo = __float2bfloat16_rn(x - __bfloat162float(hi));
}
__device__ __forceinline__ uint32_t pack2(__nv_bfloat16 lo, __nv_bfloat16 hi) {
    __nv_bfloat162 r;
    r.x = lo; r.y = hi;
    return *(uint32_t*)&r;
}

// ---------------------------------------------------------------------------
// Elementwise fp32 -> (hi, lo) bf16 split. n4 = element count / 4.
// ---------------------------------------------------------------------------
__global__ __launch_bounds__(256) void split_k(
    const float* __restrict__ in, __nv_bfloat16* __restrict__ hi,
    __nv_bfloat16* __restrict__ lo, int n4)
{
    int i = blockIdx.x * 256 + threadIdx.x;
    if (i >= n4) return;
    float4 v = ((const float4*)in)[i];
    __nv_bfloat16 h[4], l[4];
    split_bf16(v.x, h[0], l[0]);
    split_bf16(v.y, h[1], l[1]);
    split_bf16(v.z, h[2], l[2]);
    split_bf16(v.w, h[3], l[3]);
    ((uint2*)hi)[i] = *(uint2*)h;
    ((uint2*)lo)[i] = *(uint2*)l;
}

// ---------------------------------------------------------------------------
// Transpose + split: outHi/outLo[n][k] = split(in[k][n]); in is R x C.
// ---------------------------------------------------------------------------
__global__ __launch_bounds__(256) void transpose_split_k(
    const float* __restrict__ in, __nv_bfloat16* __restrict__ outHi,
    __nv_bfloat16* __restrict__ outLo, int R, int C)
{
    __shared__ float tile[32][33];
    const int tx = threadIdx.x, ty = threadIdx.y;
    const int c0 = blockIdx.x * 32, r0 = blockIdx.y * 32;
#pragma unroll
    for (int i = ty; i < 32; i += 8)
        tile[i][tx] = in[(size_t)(r0 + i) * C + c0 + tx];
    __syncthreads();
#pragma unroll
    for (int i = ty; i < 32; i += 8) {
        __nv_bfloat16 h, l;
        split_bf16(tile[tx][i], h, l);
        outHi[(size_t)(c0 + i) * R + r0 + tx] = h;
        outLo[(size_t)(c0 + i) * R + r0 + tx] = l;
    }
}

// ---------------------------------------------------------------------------
// V^T split, all (b,kvh) slices in one launch (grid.z = B_*NKV_).
// in slice: [S_, HD_] fp32 -> out slices [HD_, S_] bf16 hi/lo.
// ---------------------------------------------------------------------------
__global__ __launch_bounds__(256) void vt_split_k(
    const float* __restrict__ in, __nv_bfloat16* __restrict__ outHi,
    __nv_bfloat16* __restrict__ outLo)
{
    __shared__ float tile[32][33];
    const int tx = threadIdx.x, ty = threadIdx.y;
    const int c0 = blockIdx.x * 32, r0 = blockIdx.y * 32;
    const int sl = blockIdx.z;
    const float* src = in + (size_t)sl * S_ * HD_;
    __nv_bfloat16* dh = outHi + (size_t)sl * HD_ * S_;
    __nv_bfloat16* dl = outLo + (size_t)sl * HD_ * S_;
#pragma unroll
    for (int i = ty; i < 32; i += 8)
        tile[i][tx] = src[(size_t)(r0 + i) * HD_ + c0 + tx];
    __syncthreads();
#pragma unroll
    for (int i = ty; i < 32; i += 8) {
        __nv_bfloat16 h, l;
        split_bf16(tile[tx][i], h, l);
        dh[(size_t)(c0 + i) * S_ + r0 + tx] = h;
        dl[(size_t)(c0 + i) * S_ + r0 + tx] = l;
    }
}

// ---------------------------------------------------------------------------
// bf16x3 GEMM — round-10 structure; MMA term loop hoisted outermost so each
// accumulator's 3 products are separated by 16 independent MMAs (RAW relief).
// 8 warps, warp tile 64x32, BK=32, ldmatrix, NSTAGE=2 (2 CTAs/SM).
// ---------------------------------------------------------------------------
#define ASTRIDE 40
#define TILE_B  (128 * ASTRIDE * 2)        // 10240 bytes
#define STAGE_B (4 * TILE_B)               // 40960 bytes
#define NSTAGE  2

__global__ __launch_bounds__(256, 2) void gemm_bf16x3_k(
    const __nv_bfloat16* __restrict__ Ahi, const __nv_bfloat16* __restrict__ Alo,
    const __nv_bfloat16* __restrict__ Bhi, const __nv_bfloat16* __restrict__ Blo,
    float* __restrict__ C, int M, int N, int K)
{
    extern __shared__ char dsm[];
    const int t    = threadIdx.x;
    const int lane = t & 31, w = t >> 5;
    const int gid  = lane >> 2, tig = lane & 3;
    const int wm   = (w >> 2) * 64;
    const int wn   = (w & 3) * 32;
    const int brow = blockIdx.y * 128;
    const int bcol = blockIdx.x * 128;

    const uint32_t smBase = smem_u32(dsm);

    const int lm = lane >> 3;              // matrix index 0..3
    const int lr = lane & 7;
    const uint32_t aFragOff =
        (uint32_t)((wm + (lm & 1) * 8 + lr) * 80 + (lm >> 1) * 16);
    const uint32_t bFragOff =
        (uint32_t)((wn + (lm >> 1) * 8 + lr) * 80 + (lm & 1) * 16);

    float acc[16][4];
#pragma unroll
    for (int i = 0; i < 16; i++)
#pragma unroll
        for (int j = 0; j < 4; j++) acc[i][j] = 0.f;

    const int nk = K >> 5;

    auto issue = [&](int s, int kt) {
        const uint32_t st = smBase + s * STAGE_B;
        const int k0 = kt << 5;
        const __nv_bfloat16* srcs[4] = { Ahi, Alo, Bhi, Blo };
        const int rb[4] = { brow, brow, bcol, bcol };
#pragma unroll
        for (int m = 0; m < 4; m++) {
            const uint32_t dst = st + m * TILE_B;
#pragma unroll
            for (int i = 0; i < 2; i++) {
                const int j = i * 256 + t;
                const int r = j >> 2, kq = j & 3;
                CP_ASYNC16(dst + (uint32_t)(r * ASTRIDE + kq * 8) * 2,
                           srcs[m] + (size_t)(rb[m] + r) * K + k0 + kq * 8);
            }
        }
    };

    issue(0, 0); CP_COMMIT();
    issue(1, 1); CP_COMMIT();

    for (int kt = 0; kt < nk; kt++) {
        CP_WAIT1();
        __syncthreads();

        const int buf = kt & 1;
        const uint32_t stBase = smBase + buf * STAGE_B;
        const uint32_t aH = stBase + aFragOff;
        const uint32_t aL = aH + TILE_B;
        const uint32_t bH = stBase + 2 * TILE_B + bFragOff;
        const uint32_t bL = bH + TILE_B;

#pragma unroll
        for (int ks = 0; ks < 2; ks++) {
            const uint32_t kb = (uint32_t)(ks * 32);
            uint32_t ah[4][4], al[4][4];
#pragma unroll
            for (int mt = 0; mt < 4; mt++) {
                LDMATRIX_X4(ah[mt][0], ah[mt][1], ah[mt][2], ah[mt][3],
                            aH + mt * 1280 + kb);
                LDMATRIX_X4(al[mt][0], al[mt][1], al[mt][2], al[mt][3],
                            aL + mt * 1280 + kb);
            }
            uint32_t bh[4][2], bl[4][2];
#pragma unroll
            for (int jj = 0; jj < 2; jj++) {
                uint32_t q0, q1, q2, q3;
                LDMATRIX_X4(q0, q1, q2, q3, bH + jj * 1280 + kb);
                bh[2 * jj][0] = q0; bh[2 * jj][1] = q1;
                bh[2 * jj + 1][0] = q2; bh[2 * jj + 1][1] = q3;
                LDMATRIX_X4(q0, q1, q2, q3, bL + jj * 1280 + kb);
                bl[2 * jj][0] = q0; bl[2 * jj][1] = q1;
                bl[2 * jj + 1][0] = q2; bl[2 * jj + 1][1] = q3;
            }
            // term-major ordering: hh sweep, hl sweep, lh sweep.
#pragma unroll
            for (int nt = 0; nt < 4; nt++)
#pragma unroll
                for (int mt = 0; mt < 4; mt++) {
                    float* d = acc[nt * 4 + mt];
                    mma_bf16(d[0], d[1], d[2], d[3],
                             ah[mt][0], ah[mt][1], ah[mt][2], ah[mt][3],
                             bh[nt][0], bh[nt][1]);
                }
#pragma unroll
            for (int nt = 0; nt < 4; nt++)
#pragma unroll
                for (int mt = 0; mt < 4; mt++) {
                    float* d = acc[nt * 4 + mt];
                    mma_bf16(d[0], d[1], d[2], d[3],
                             ah[mt][0], ah[mt][1], ah[mt][2], ah[mt][3],
                             bl[nt][0], bl[nt][1]);
                }
#pragma unroll
            for (int nt = 0; nt < 4; nt++)
#pragma unroll
                for (int mt = 0; mt < 4; mt++) {
                    float* d = acc[nt * 4 + mt];
                    mma_bf16(d[0], d[1], d[2], d[3],
                             al[mt][0], al[mt][1], al[mt][2], al[mt][3],
                             bh[nt][0], bh[nt][1]);
                }
        }
        __syncthreads();                   // required: NSTAGE=2 reuses buf
        if (kt + 2 < nk) issue(buf, kt + 2);
        CP_COMMIT();
    }

#pragma unroll
    for (int nt = 0; nt < 4; nt++) {
#pragma unroll
        for (int mt = 0; mt < 4; mt++) {
            const float* d = acc[nt * 4 + mt];
            const int r0 = brow + wm + mt * 16 + gid;
            const int c0 = bcol + wn + nt * 8 + 2 * tig;
            *(float2*)&C[(size_t)r0 * N + c0]       = make_float2(d[0], d[1]);
            *(float2*)&C[(size_t)(r0 + 8) * N + c0] = make_float2(d[2], d[3]);
        }
    }
}

// ---------------------------------------------------------------------------
// Fused per-head RMSNorm (+ RoPE for q/k). Emits bf16 hi/lo for Q and K,
// fp32 for V (V^T split happens in vt_split_k).
// ---------------------------------------------------------------------------
__global__ __launch_bounds__(256) void qkv_post_k(
    const float* __restrict__ qkv, const int* __restrict__ positions,
    const float* __restrict__ qw, const float* __restrict__ kw,
    __nv_bfloat16* __restrict__ QhO, __nv_bfloat16* __restrict__ QlO,
    __nv_bfloat16* __restrict__ KhO, __nv_bfloat16* __restrict__ KlO,
    float* __restrict__ V)
{
    const int h   = blockIdx.x;   // 0..11
    const int s   = blockIdx.y;
    const int b   = blockIdx.z;
    const int tid = threadIdx.x;  // 0..255

    __shared__ float red[8];
    __shared__ float sy[256];

    const float* row = qkv + (size_t)(b * S_ + s) * QKV_N;

    int off;
    float w = 1.0f;
    if (h < 8)       { off = h * 256;                w = qw[tid]; }
    else if (h < 10) { off = 2048 + (h - 8) * 256;   w = kw[tid]; }
    else             { off = 2560 + (h - 10) * 256; }

    float x = row[off + tid];
    float v = x * x;
#pragma unroll
    for (int o = 16; o > 0; o >>= 1) v += __shfl_xor_sync(0xffffffffu, v, o);
    if ((tid & 31) == 0) red[tid >> 5] = v;
    __syncthreads();
    float ss = 0.f;
#pragma unroll
    for (int i = 0; i < 8; i++) ss += red[i];

    float y = x * rsqrtf(ss * (1.0f / 256.0f) + 1e-6f) * w;

    if (h >= 10) {
        V[((size_t)(b * NKV_ + (h - 10)) * S_ + s) * HD_ + tid] = y;
        return;
    }

    sy[tid] = y;
    __syncthreads();

    if (tid < 128) {
        float invf = powf(1000000.0f, -(float)tid * (1.0f / 128.0f));
        float f    = (float)positions[b * S_ + s] * invf;
        float si, co;
        sincosf(f, &si, &co);
        float x1 = sy[tid];
        float x2 = sy[tid + 128];
        float o1 = x1 * co - x2 * si;
        float o2 = x2 * co + x1 * si;
        __nv_bfloat16 h1, l1, h2, l2;
        split_bf16(o1, h1, l1);
        split_bf16(o2, h2, l2);
        if (h < 8) {
            size_t base = ((size_t)(b * NH_ + h) * S_ + s) * HD_;
            QhO[base + tid] = h1;       QlO[base + tid] = l1;
            QhO[base + tid + 128] = h2; QlO[base + tid + 128] = l2;
        } else {
            size_t base = ((size_t)(b * NKV_ + (h - 8)) * S_ + s) * HD_;
            KhO[base + tid] = h1;       KlO[base + tid] = l1;
            KhO[base + tid + 128] = h2; KlO[base + tid + 128] = l2;
        }
    }
}

// ---------------------------------------------------------------------------
// Flash attention on HMMA with bf16x3 emulation — ROUND-10 VERSION VERBATIM
// (best measured): scalar LDS fragments, double-buffered BK=32 KV,
// 217 KB smem, 1 CTA/SM, heavy-first scheduling.
// ---------------------------------------------------------------------------
#define DWQ     132                     // u32 words per Q/K smem row (264 bf16)
#define QROWB   528                     // bytes per Q/K smem row
#define VROWB   80                      // bytes per Vt smem row (40 bf16)
#define SM_QH   0
#define SM_QL   33792                   // 64*528
#define SM_ST0  67584
#define STG_B   74752                   // K(16896*2) + Vt(20480*2)
#define ST_KH   0
#define ST_KL   16896
#define ST_VTH  33792
#define ST_VTL  54272
#define ATTN_SMEM_TOTAL (SM_ST0 + 2 * STG_B)   // 217088

__global__ __launch_bounds__(128, 1) void attn_mma_k(
    const __nv_bfloat16* __restrict__ Qh, const __nv_bfloat16* __restrict__ Ql,
    const __nv_bfloat16* __restrict__ Kh, const __nv_bfloat16* __restrict__ Kl,
    const __nv_bfloat16* __restrict__ Vth, const __nv_bfloat16* __restrict__ Vtl,
    __nv_bfloat16* __restrict__ Ohi, __nv_bfloat16* __restrict__ Olo)
{
    extern __shared__ char dsm[];
    const int t    = threadIdx.x;
    const int lane = t & 31, w = t >> 5;
    const int gid  = lane >> 2, tig = lane & 3;
    const int h    = blockIdx.y, b = blockIdx.z;
    const int qt   = gridDim.x - 1 - blockIdx.x;   // heavy tiles first
    const int q0   = qt * 64;
    const int kvh  = h >> 2;
    const uint32_t smb = smem_u32(dsm);

    const __nv_bfloat16* qhg = Qh + ((size_t)(b * NH_ + h) * S_ + q0) * HD_;
    const __nv_bfloat16* qlg = Ql + ((size_t)(b * NH_ + h) * S_ + q0) * HD_;
    const __nv_bfloat16* khg = Kh + (size_t)(b * NKV_ + kvh) * S_ * HD_;
    const __nv_bfloat16* klg = Kl + (size_t)(b * NKV_ + kvh) * S_ * HD_;
    const __nv_bfloat16* vhg = Vth + (size_t)(b * NKV_ + kvh) * HD_ * S_;
    const __nv_bfloat16* vlg = Vtl + (size_t)(b * NKV_ + kvh) * HD_ * S_;

    // ---- stage Q (hi+lo): 64 rows x 256 bf16 each ----
#pragma unroll
    for (int i = 0; i < 16; i++) {
        const int j = i * 128 + t;             // 0..2047
        const int r = j >> 5, c = j & 31;
        CP_ASYNC16(smb + SM_QH + r * QROWB + c * 16, qhg + (size_t)r * HD_ + c * 8);
        CP_ASYNC16(smb + SM_QL + r * QROWB + c * 16, qlg + (size_t)r * HD_ + c * 8);
    }

    const int nt = qt * 2 + 2;                // K-tiles of 32

    auto issueKV = [&](int kt) {
        const uint32_t st = smb + SM_ST0 + (kt & 1) * STG_B;
        const int k0 = kt << 5;
#pragma unroll
        for (int i = 0; i < 8; i++) {
            const int j = i * 128 + t;         // 0..1023
            const int r = j >> 5, c = j & 31;  // K: row, 8-elt chunk
            CP_ASYNC16(st + ST_KH + r * QROWB + c * 16,
                       khg + (size_t)(k0 + r) * HD_ + c * 8);
            CP_ASYNC16(st + ST_KL + r * QROWB + c * 16,
                       klg + (size_t)(k0 + r) * HD_ + c * 8);
            const int vr = j >> 2, vc = j & 3; // Vt: row d, 8-elt chunk
            CP_ASYNC16(st + ST_VTH + vr * VROWB + vc * 16,
                       vhg + (size_t)vr * S_ + k0 + vc * 8);
            CP_ASYNC16(st + ST_VTL + vr * VROWB + vc * 16,
                       vlg + (size_t)vr * S_ + k0 + vc * 8);
        }
    };

    issueKV(0); CP_COMMIT();

    float O[32][4];
#pragma unroll
    for (int n = 0; n < 32; n++)
#pragma unroll
        for (int i = 0; i < 4; i++) O[n][i] = 0.f;
    float m0 = -1e30f, m1 = -1e30f, l0 = 0.f, l1 = 0.f;

    const int ar0 = (w * 16 + gid) * DWQ;
    const int ar1 = ar0 + 8 * DWQ;
    const uint32_t* QHW = (const uint32_t*)(dsm + SM_QH);
    const uint32_t* QLW = (const uint32_t*)(dsm + SM_QL);

    for (int kt = 0; kt < nt; kt++) {
        const bool more = (kt + 1 < nt);
        if (more) { issueKV(kt + 1); CP_COMMIT(); }
        if (more) CP_WAIT1(); else CP_WAIT0();
        __syncthreads();

        const char* st = dsm + SM_ST0 + (kt & 1) * STG_B;
        const uint32_t* KHW = (const uint32_t*)(st + ST_KH);
        const uint32_t* KLW = (const uint32_t*)(st + ST_KL);
        const uint32_t* VHW = (const uint32_t*)(st + ST_VTH);
        const uint32_t* VLW = (const uint32_t*)(st + ST_VTL);
        const int k0 = kt << 5;

        // ---- S = Q K^T (bf16x3, two accumulator sets for ILP) ----
        float S1[4][4], S2[4][4];
#pragma unroll
        for (int j = 0; j < 4; j++)
#pragma unroll
            for (int i = 0; i < 4; i++) { S1[j][i] = 0.f; S2[j][i] = 0.f; }

#pragma unroll
        for (int ks = 0; ks < 16; ks++) {
            const int kwd = ks * 8 + tig;
            const uint32_t ah0 = QHW[ar0 + kwd], ah1 = QHW[ar1 + kwd];
            const uint32_t ah2 = QHW[ar0 + kwd + 4], ah3 = QHW[ar1 + kwd + 4];
            const uint32_t al0 = QLW[ar0 + kwd], al1 = QLW[ar1 + kwd];
            const uint32_t al2 = QLW[ar0 + kwd + 4], al3 = QLW[ar1 + kwd + 4];
#pragma unroll
            for (int j = 0; j < 4; j++) {
                const int bo = (8 * j + gid) * DWQ + kwd;
                const uint32_t bh0 = KHW[bo], bh1 = KHW[bo + 4];
                const uint32_t bl0 = KLW[bo], bl1 = KLW[bo + 4];
                mma_bf16(S1[j][0], S1[j][1], S1[j][2], S1[j][3],
                         ah0, ah1, ah2, ah3, bh0, bh1);
                mma_bf16(S2[j][0], S2[j][1], S2[j][2], S2[j][3],
                         ah0, ah1, ah2, ah3, bl0, bl1);
                mma_bf16(S2[j][0], S2[j][1], S2[j][2], S2[j][3],
                         al0, al1, al2, al3, bh0, bh1);
            }
        }

        // ---- online softmax ----
        float p[4][4];
        const bool needmask = (k0 + 31) > (q0 + w * 16);
        float tm0 = -1e30f, tm1 = -1e30f;
#pragma unroll
        for (int j = 0; j < 4; j++) {
#pragma unroll
            for (int i = 0; i < 4; i++) {
                float s = S1[j][i] + S2[j][i];
                if (needmask) {
                    const int col = k0 + 8 * j + 2 * tig + (i & 1);
                    const int row = q0 + w * 16 + gid + ((i >= 2) ? 8 : 0);
                    if (col > row) s = -1e30f;
                }
                p[j][i] = s;
                if (i < 2) tm0 = fmaxf(tm0, s); else tm1 = fmaxf(tm1, s);
            }
        }
        tm0 = fmaxf(tm0, __shfl_xor_sync(0xffffffffu, tm0, 1));
        tm0 = fmaxf(tm0, __shfl_xor_sync(0xffffffffu, tm0, 2));
        tm1 = fmaxf(tm1, __shfl_xor_sync(0xffffffffu, tm1, 1));
        tm1 = fmaxf(tm1, __shfl_xor_sync(0xffffffffu, tm1, 2));

        const float mn0 = fmaxf(m0, tm0), mn1 = fmaxf(m1, tm1);
        const float a0 = __expf(m0 - mn0), a1 = __expf(m1 - mn1);

        float sum0 = 0.f, sum1 = 0.f;
#pragma unroll
        for (int j = 0; j < 4; j++) {
            p[j][0] = __expf(p[j][0] - mn0); sum0 += p[j][0];
            p[j][1] = __expf(p[j][1] - mn0); sum0 += p[j][1];
            p[j][2] = __expf(p[j][2] - mn1); sum1 += p[j][2];
            p[j][3] = __expf(p[j][3] - mn1); sum1 += p[j][3];
        }
        sum0 += __shfl_xor_sync(0xffffffffu, sum0, 1);
        sum0 += __shfl_xor_sync(0xffffffffu, sum0, 2);
        sum1 += __shfl_xor_sync(0xffffffffu, sum1, 1);
        sum1 += __shfl_xor_sync(0xffffffffu, sum1, 2);

        l0 = l0 * a0 + sum0;  m0 = mn0;
        l1 = l1 * a1 + sum1;  m1 = mn1;

#pragma unroll
        for (int n = 0; n < 32; n++) {
            O[n][0] *= a0; O[n][1] *= a0;
            O[n][2] *= a1; O[n][3] *= a1;
        }

        // ---- P fragments (hi/lo split, direct from registers) ----
        uint32_t ph[2][4], pl[2][4];
#pragma unroll
        for (int kk = 0; kk < 2; kk++) {
#pragma unroll
            for (int q = 0; q < 4; q++) {
                const int j = 2 * kk + (q >> 1);
                const int i0 = (q & 1) * 2;
                __nv_bfloat16 h0, lo0, h1, lo1;
                split_bf16(p[j][i0], h0, lo0);
                split_bf16(p[j][i0 + 1], h1, lo1);
                ph[kk][q] = pack2(h0, h1);
                pl[kk][q] = pack2(lo0, lo1);
            }
        }

        // ---- O += P V (bf16x3) ----
#pragma unroll
        for (int n = 0; n < 32; n++) {
#pragma unroll
            for (int kk = 0; kk < 2; kk++) {
                const int bo = (8 * n + gid) * 20 + kk * 8 + tig;
                const uint32_t bh0 = VHW[bo], bh1 = VHW[bo + 4];
                const uint32_t bl0 = VLW[bo], bl1 = VLW[bo + 4];
                mma_bf16(O[n][0], O[n][1], O[n][2], O[n][3],
                         ph[kk][0], ph[kk][1], ph[kk][2], ph[kk][3], bh0, bh1);
                mma_bf16(O[n][0], O[n][1], O[n][2], O[n][3],
                         ph[kk][0], ph[kk][1], ph[kk][2], ph[kk][3], bl0, bl1);
                mma_bf16(O[n][0], O[n][1], O[n][2], O[n][3],
                         pl[kk][0], pl[kk][1], pl[kk][2], pl[kk][3], bh0, bh1);
            }
        }
        __syncthreads();
    }

    // ---- epilogue: O/l -> bf16 hi/lo -> global ----
    const float inv0 = 1.f / l0, inv1 = 1.f / l1;
    const size_t ro0 = (size_t)(b * S_ + q0 + w * 16 + gid) * (NH_ * HD_)
                       + h * HD_;
    const size_t ro1 = ro0 + (size_t)8 * (NH_ * HD_);
#pragma unroll
    for (int n = 0; n < 32; n++) {
        const int col = 8 * n + 2 * tig;
        __nv_bfloat16 h0, lo0, h1, lo1;
        split_bf16(O[n][0] * inv0, h0, lo0);
        split_bf16(O[n][1] * inv0, h1, lo1);
        *(uint32_t*)(Ohi + ro0 + col) = pack2(h0, h1);
        *(uint32_t*)(Olo + ro0 + col) = pack2(lo0, lo1);
        split_bf16(O[n][2] * inv1, h0, lo0);
        split_bf16(O[n][3] * inv1, h1, lo1);
        *(uint32_t*)(Ohi + ro1 + col) = pack2(h0, h1);
        *(uint32_t*)(Olo + ro1 + col) = pack2(lo0, lo1);
    }
}

// ---------------------------------------------------------------------------
// Launch
// ---------------------------------------------------------------------------
extern "C" void kernel_launch(void* const* d_in, const int* in_sizes, int n_in,
                              void* d_out, int out_size)
{
    const float* hidden    = (const float*)d_in[0];
    const int*   positions = (const int*)  d_in[1];
    const float* w_qkv     = (const float*)d_in[2];
    const float* w_o       = (const float*)d_in[3];
    const float* q_norm_w  = (const float*)d_in[4];
    const float* k_norm_w  = (const float*)d_in[5];
    float*       out       = (float*)d_out;

    float *qkv, *V;
    __nv_bfloat16 *qh, *ql, *kh, *kl, *vth, *vtl;
    __nv_bfloat16 *hidH, *hidL, *attH, *attL, *wqkH, *wqkL, *woH, *woL;
    cudaGetSymbolAddress((void**)&qkv,  g_qkv);
    cudaGetSymbolAddress((void**)&V,    g_v);
    cudaGetSymbolAddress((void**)&qh,   g_qh);
    cudaGetSymbolAddress((void**)&ql,   g_ql);
    cudaGetSymbolAddress((void**)&kh,   g_kh);
    cudaGetSymbolAddress((void**)&kl,   g_kl);
    cudaGetSymbolAddress((void**)&vth,  g_vth);
    cudaGetSymbolAddress((void**)&vtl,  g_vtl);
    cudaGetSymbolAddress((void**)&hidH, g_hid_hi);
    cudaGetSymbolAddress((void**)&hidL, g_hid_lo);
    cudaGetSymbolAddress((void**)&attH, g_attn_hi);
    cudaGetSymbolAddress((void**)&attL, g_attn_lo);
    cudaGetSymbolAddress((void**)&wqkH, g_wqkT_hi);
    cudaGetSymbolAddress((void**)&wqkL, g_wqkT_lo);
    cudaGetSymbolAddress((void**)&woH,  g_woT_hi);
    cudaGetSymbolAddress((void**)&woL,  g_woT_lo);

    const int GEMM_SMEM = NSTAGE * STAGE_B;      // 81920
    cudaFuncSetAttribute(gemm_bf16x3_k,
        cudaFuncAttributeMaxDynamicSharedMemorySize, GEMM_SMEM);
    cudaFuncSetAttribute(attn_mma_k,
        cudaFuncAttributeMaxDynamicSharedMemorySize, ATTN_SMEM_TOTAL);

    // 0) operand preparation
    {
        const int n4 = (MROWS * HIDDEN_) / 4;
        split_k<<<(n4 + 255) / 256, 256>>>(hidden, hidH, hidL, n4);
    }
    transpose_split_k<<<dim3(QKV_N / 32, HIDDEN_ / 32), dim3(32, 8)>>>(
        w_qkv, wqkH, wqkL, HIDDEN_, QKV_N);
    transpose_split_k<<<dim3((NH_ * HD_) / 32, HIDDEN_ / 32), dim3(32, 8)>>>(
        w_o, woH, woL, HIDDEN_, NH_ * HD_);

    // 1) QKV projection
    gemm_bf16x3_k<<<dim3(QKV_N / 128, MROWS / 128), 256, GEMM_SMEM>>>(
        hidH, hidL, wqkH, wqkL, qkv, MROWS, QKV_N, HIDDEN_);

    // 2) rmsnorm + rope -> Q/K bf16 hi/lo, V fp32
    qkv_post_k<<<dim3(12, S_, B_), 256>>>(
        qkv, positions, q_norm_w, k_norm_w, qh, ql, kh, kl, V);

    // 2b) V^T split, all slices in one launch
    vt_split_k<<<dim3(HD_ / 32, S_ / 32, B_ * NKV_), dim3(32, 8)>>>(
        V, vth, vtl);

    // 3) causal attention (round-10 config, best measured)
    attn_mma_k<<<dim3(S_ / 64, NH_, B_), 128, ATTN_SMEM_TOTAL>>>(
        qh, ql, kh, kl, vth, vtl, attH, attL);

    // 4) output projection
    gemm_bf16x3_k<<<dim3((NH_ * HD_) / 128, MROWS / 128), 256, GEMM_SMEM>>>(
        attH, attL, woH, woL, out, MROWS, NH_ * HD_, HIDDEN_);
}

// round 15
// speedup vs baseline: 1.6520x; 1.0818x over previous
#include <cuda_runtime.h>
#include <cuda_bf16.h>
#include <math.h>
#include <stdint.h>

// ---------------------------------------------------------------------------
// Problem constants
// ---------------------------------------------------------------------------
#define B_      2
#define S_      2048
#define HIDDEN_ 2048
#define NH_     8
#define NKV_    2
#define HD_     256
#define QKV_N   3072          // (8 + 2*2) * 256
#define MROWS   (B_ * S_)     // 4096

// ---------------------------------------------------------------------------
// Scratch (device globals; no allocation allowed)
// ---------------------------------------------------------------------------
__device__ float         g_qkv    [(size_t)MROWS * QKV_N];
__device__ float         g_v      [(size_t)B_ * NKV_ * S_ * HD_];   // fp32 V
__device__ __nv_bfloat16 g_qh     [(size_t)B_ * NH_  * S_ * HD_];
__device__ __nv_bfloat16 g_ql     [(size_t)B_ * NH_  * S_ * HD_];
__device__ __nv_bfloat16 g_kh     [(size_t)B_ * NKV_ * S_ * HD_];
__device__ __nv_bfloat16 g_kl     [(size_t)B_ * NKV_ * S_ * HD_];
__device__ __nv_bfloat16 g_vth    [(size_t)B_ * NKV_ * HD_ * S_];   // V^T [d][s]
__device__ __nv_bfloat16 g_vtl    [(size_t)B_ * NKV_ * HD_ * S_];
__device__ __nv_bfloat16 g_hid_hi [(size_t)MROWS * HIDDEN_];
__device__ __nv_bfloat16 g_hid_lo [(size_t)MROWS * HIDDEN_];
__device__ __nv_bfloat16 g_attn_hi[(size_t)MROWS * (NH_ * HD_)];
__device__ __nv_bfloat16 g_attn_lo[(size_t)MROWS * (NH_ * HD_)];
__device__ __nv_bfloat16 g_wqkT_hi[(size_t)QKV_N * HIDDEN_];
__device__ __nv_bfloat16 g_wqkT_lo[(size_t)QKV_N * HIDDEN_];
__device__ __nv_bfloat16 g_woT_hi [(size_t)HIDDEN_ * (NH_ * HD_)];
__device__ __nv_bfloat16 g_woT_lo [(size_t)HIDDEN_ * (NH_ * HD_)];

// ---------------------------------------------------------------------------
// Helpers
// ---------------------------------------------------------------------------
__device__ __forceinline__ uint32_t smem_u32(const void* p) {
    uint32_t a;
    asm("{ .reg .u64 t; cvta.to.shared.u64 t, %1; cvt.u32.u64 %0, t; }"
        : "=r"(a) : "l"(p));
    return a;
}

#define CP_ASYNC16(sm, gp) \
    asm volatile("cp.async.cg.shared.global [%0], [%1], 16;" \
        :: "r"(sm), "l"(gp) : "memory")
#define CP_COMMIT() asm volatile("cp.async.commit_group;" ::: "memory")
#define CP_WAIT0()  asm volatile("cp.async.wait_group 0;"  ::: "memory")
#define CP_WAIT1()  asm volatile("cp.async.wait_group 1;"  ::: "memory")

#define LDMATRIX_X4(r0, r1, r2, r3, addr) \
    asm volatile("ldmatrix.sync.aligned.m8n8.x4.shared.b16 {%0,%1,%2,%3}, [%4];" \
        : "=r"(r0), "=r"(r1), "=r"(r2), "=r"(r3) : "r"(addr))

__device__ __forceinline__ void mma_bf16(
    float& d0, float& d1, float& d2, float& d3,
    uint32_t a0, uint32_t a1, uint32_t a2, uint32_t a3,
    uint32_t b0, uint32_t b1)
{
    asm volatile(
        "mma.sync.aligned.m16n8k16.row.col.f32.bf16.bf16.f32 "
        "{%0,%1,%2,%3}, {%4,%5,%6,%7}, {%8,%9}, {%0,%1,%2,%3};"
        : "+f"(d0), "+f"(d1), "+f"(d2), "+f"(d3)
        : "r"(a0), "r"(a1), "r"(a2), "r"(a3), "r"(b0), "r"(b1));
}

__device__ __forceinline__ void split_bf16(float x, __nv_bfloat16& hi,
                                           __nv_bfloat16& lo) {
    hi = __float2bfloat16_rn(x);
    lo = __float2bfloat16_rn(x - __bfloat162float(hi));
}
__device__ __forceinline__ uint32_t pack2(__nv_bfloat16 lo, __nv_bfloat16 hi) {
    __nv_bfloat162 r;
    r.x = lo; r.y = hi;
    return *(uint32_t*)&r;
}

// ---------------------------------------------------------------------------
// Elementwise fp32 -> (hi, lo) bf16 split. n4 = element count / 4.
// ---------------------------------------------------------------------------
__global__ __launch_bounds__(256) void split_k(
    const float* __restrict__ in, __nv_bfloat16* __restrict__ hi,
    __nv_bfloat16* __restrict__ lo, int n4)
{
    int i = blockIdx.x * 256 + threadIdx.x;
    if (i >= n4) return;
    float4 v = ((const float4*)in)[i];
    __nv_bfloat16 h[4], l[4];
    split_bf16(v.x, h[0], l[0]);
    split_bf16(v.y, h[1], l[1]);
    split_bf16(v.z, h[2], l[2]);
    split_bf16(v.w, h[3], l[3]);
    ((uint2*)hi)[i] = *(uint2*)h;
    ((uint2*)lo)[i] = *(uint2*)l;
}

// ---------------------------------------------------------------------------
// Transpose + split: outHi/outLo[n][k] = split(in[k][n]); in is R x C.
// ---------------------------------------------------------------------------
__global__ __launch_bounds__(256) void transpose_split_k(
    const float* __restrict__ in, __nv_bfloat16* __restrict__ outHi,
    __nv_bfloat16* __restrict__ outLo, int R, int C)
{
    __shared__ float tile[32][33];
    const int tx = threadIdx.x, ty = threadIdx.y;
    const int c0 = blockIdx.x * 32, r0 = blockIdx.y * 32;
#pragma unroll
    for (int i = ty; i < 32; i += 8)
        tile[i][tx] = in[(size_t)(r0 + i) * C + c0 + tx];
    __syncthreads();
#pragma unroll
    for (int i = ty; i < 32; i += 8) {
        __nv_bfloat16 h, l;
        split_bf16(tile[tx][i], h, l);
        outHi[(size_t)(c0 + i) * R + r0 + tx] = h;
        outLo[(size_t)(c0 + i) * R + r0 + tx] = l;
    }
}

// ---------------------------------------------------------------------------
// V^T split, all (b,kvh) slices in one launch (grid.z = B_*NKV_).
// ---------------------------------------------------------------------------
__global__ __launch_bounds__(256) void vt_split_k(
    const float* __restrict__ in, __nv_bfloat16* __restrict__ outHi,
    __nv_bfloat16* __restrict__ outLo)
{
    __shared__ float tile[32][33];
    const int tx = threadIdx.x, ty = threadIdx.y;
    const int c0 = blockIdx.x * 32, r0 = blockIdx.y * 32;
    const int sl = blockIdx.z;
    const float* src = in + (size_t)sl * S_ * HD_;
    __nv_bfloat16* dh = outHi + (size_t)sl * HD_ * S_;
    __nv_bfloat16* dl = outLo + (size_t)sl * HD_ * S_;
#pragma unroll
    for (int i = ty; i < 32; i += 8)
        tile[i][tx] = src[(size_t)(r0 + i) * HD_ + c0 + tx];
    __syncthreads();
#pragma unroll
    for (int i = ty; i < 32; i += 8) {
        __nv_bfloat16 h, l;
        split_bf16(tile[tx][i], h, l);
        dh[(size_t)(c0 + i) * S_ + r0 + tx] = h;
        dl[(size_t)(c0 + i) * S_ + r0 + tx] = l;
    }
}

// ---------------------------------------------------------------------------
// bf16x3 GEMM: 8 warps, warp tile 64x32, BK=32, ldmatrix fragments.
// XOR-swizzled dense 64B rows (no padding): phys_chunk = c ^ ((r>>1)&3).
// Tile 8192 B, stage 32768 B, NSTAGE=3 -> 96 KB -> 2 CTAs/SM with the
// round-9-proven 3-stage pipeline (WAIT1, issue(kt+2) after barrier).
// ---------------------------------------------------------------------------
#define TILE_B  8192                       // 128 rows * 64 B, dense
#define STAGE_B (4 * TILE_B)               // 32768
#define NSTAGE  3

__global__ __launch_bounds__(256, 2) void gemm_bf16x3_k(
    const __nv_bfloat16* __restrict__ Ahi, const __nv_bfloat16* __restrict__ Alo,
    const __nv_bfloat16* __restrict__ Bhi, const __nv_bfloat16* __restrict__ Blo,
    float* __restrict__ C, int M, int N, int K)
{
    extern __shared__ char dsm[];
    const int t    = threadIdx.x;
    const int lane = t & 31, w = t >> 5;
    const int gid  = lane >> 2, tig = lane & 3;
    const int wm   = (w >> 2) * 64;
    const int wn   = (w & 3) * 32;
    const int brow = blockIdx.y * 128;
    const int bcol = blockIdx.x * 128;

    const uint32_t smBase = smem_u32(dsm);

    const int lm = lane >> 3;              // matrix index 0..3
    const int lr = lane & 7;
    const int sw = (lr >> 1) & 3;          // lane-constant swizzle term

    // fragment row byte-offsets (within a tile); chunk offsets per ks below
    const uint32_t aRowOff = (uint32_t)(wm + (lm & 1) * 8 + lr) * 64;
    const uint32_t bRowOff = (uint32_t)(wn + (lm >> 1) * 8 + lr) * 64;
    const int cbitA = lm >> 1;             // A k-half bit
    const int cbitB = lm & 1;              // B k-half bit
    // physical chunk offsets for ks = 0,1
    const uint32_t aCk0 = (uint32_t)(((0 | cbitA) ^ sw) * 16);
    const uint32_t aCk1 = (uint32_t)(((2 | cbitA) ^ sw) * 16);
    const uint32_t bCk0 = (uint32_t)(((0 | cbitB) ^ sw) * 16);
    const uint32_t bCk1 = (uint32_t)(((2 | cbitB) ^ sw) * 16);

    float acc[16][4];
#pragma unroll
    for (int i = 0; i < 16; i++)
#pragma unroll
        for (int j = 0; j < 4; j++) acc[i][j] = 0.f;

    const int nk = K >> 5;

    auto issue = [&](int s, int kt) {
        const uint32_t st = smBase + s * STAGE_B;
        const int k0 = kt << 5;
        const __nv_bfloat16* srcs[4] = { Ahi, Alo, Bhi, Blo };
        const int rb[4] = { brow, brow, bcol, bcol };
#pragma unroll
        for (int m = 0; m < 4; m++) {
            const uint32_t dst = st + m * TILE_B;
#pragma unroll
            for (int i = 0; i < 2; i++) {
                const int j = i * 256 + t;
                const int r = j >> 2, kq = j & 3;
                const uint32_t off =
                    (uint32_t)(r * 64) +
                    (uint32_t)(((kq ^ ((r >> 1) & 3))) * 16);
                CP_ASYNC16(dst + off,
                           srcs[m] + (size_t)(rb[m] + r) * K + k0 + kq * 8);
            }
        }
    };

    issue(0, 0); CP_COMMIT();
    issue(1, 1); CP_COMMIT();

    for (int kt = 0; kt < nk; kt++) {
        CP_WAIT1();
        __syncthreads();

        if (kt + 2 < nk) issue((kt + 2) % NSTAGE, kt + 2);
        CP_COMMIT();

        const int buf = kt % NSTAGE;
        const uint32_t stBase = smBase + buf * STAGE_B;
        const uint32_t aH = stBase + aRowOff;
        const uint32_t aL = aH + TILE_B;
        const uint32_t bH = stBase + 2 * TILE_B + bRowOff;
        const uint32_t bL = bH + TILE_B;

#pragma unroll
        for (int ks = 0; ks < 2; ks++) {
            const uint32_t aCk = ks ? aCk1 : aCk0;
            const uint32_t bCk = ks ? bCk1 : bCk0;
            uint32_t ah[4][4], al[4][4];
#pragma unroll
            for (int mt = 0; mt < 4; mt++) {
                LDMATRIX_X4(ah[mt][0], ah[mt][1], ah[mt][2], ah[mt][3],
                            aH + mt * 1024 + aCk);
                LDMATRIX_X4(al[mt][0], al[mt][1], al[mt][2], al[mt][3],
                            aL + mt * 1024 + aCk);
            }
            uint32_t bh[4][2], bl[4][2];
#pragma unroll
            for (int jj = 0; jj < 2; jj++) {
                uint32_t q0, q1, q2, q3;
                LDMATRIX_X4(q0, q1, q2, q3, bH + jj * 1024 + bCk);
                bh[2 * jj][0] = q0; bh[2 * jj][1] = q1;
                bh[2 * jj + 1][0] = q2; bh[2 * jj + 1][1] = q3;
                LDMATRIX_X4(q0, q1, q2, q3, bL + jj * 1024 + bCk);
                bl[2 * jj][0] = q0; bl[2 * jj][1] = q1;
                bl[2 * jj + 1][0] = q2; bl[2 * jj + 1][1] = q3;
            }
            // term-major ordering: hh sweep, hl sweep, lh sweep.
#pragma unroll
            for (int nt = 0; nt < 4; nt++)
#pragma unroll
                for (int mt = 0; mt < 4; mt++) {
                    float* d = acc[nt * 4 + mt];
                    mma_bf16(d[0], d[1], d[2], d[3],
                             ah[mt][0], ah[mt][1], ah[mt][2], ah[mt][3],
                             bh[nt][0], bh[nt][1]);
                }
#pragma unroll
            for (int nt = 0; nt < 4; nt++)
#pragma unroll
                for (int mt = 0; mt < 4; mt++) {
                    float* d = acc[nt * 4 + mt];
                    mma_bf16(d[0], d[1], d[2], d[3],
                             ah[mt][0], ah[mt][1], ah[mt][2], ah[mt][3],
                             bl[nt][0], bl[nt][1]);
                }
#pragma unroll
            for (int nt = 0; nt < 4; nt++)
#pragma unroll
                for (int mt = 0; mt < 4; mt++) {
                    float* d = acc[nt * 4 + mt];
                    mma_bf16(d[0], d[1], d[2], d[3],
                             al[mt][0], al[mt][1], al[mt][2], al[mt][3],
                             bh[nt][0], bh[nt][1]);
                }
        }
        // no trailing barrier: with NSTAGE=3 the next iteration's top
        // barrier orders reads(kt) before writes(kt+3). (round-9-proven)
    }

#pragma unroll
    for (int nt = 0; nt < 4; nt++) {
#pragma unroll
        for (int mt = 0; mt < 4; mt++) {
            const float* d = acc[nt * 4 + mt];
            const int r0 = brow + wm + mt * 16 + gid;
            const int c0 = bcol + wn + nt * 8 + 2 * tig;
            *(float2*)&C[(size_t)r0 * N + c0]       = make_float2(d[0], d[1]);
            *(float2*)&C[(size_t)(r0 + 8) * N + c0] = make_float2(d[2], d[3]);
        }
    }
}

// ---------------------------------------------------------------------------
// Fused per-head RMSNorm (+ RoPE for q/k). Emits bf16 hi/lo for Q and K,
// fp32 for V (V^T split happens in vt_split_k).
// ---------------------------------------------------------------------------
__global__ __launch_bounds__(256) void qkv_post_k(
    const float* __restrict__ qkv, const int* __restrict__ positions,
    const float* __restrict__ qw, const float* __restrict__ kw,
    __nv_bfloat16* __restrict__ QhO, __nv_bfloat16* __restrict__ QlO,
    __nv_bfloat16* __restrict__ KhO, __nv_bfloat16* __restrict__ KlO,
    float* __restrict__ V)
{
    const int h   = blockIdx.x;   // 0..11
    const int s   = blockIdx.y;
    const int b   = blockIdx.z;
    const int tid = threadIdx.x;  // 0..255

    __shared__ float red[8];
    __shared__ float sy[256];

    const float* row = qkv + (size_t)(b * S_ + s) * QKV_N;

    int off;
    float w = 1.0f;
    if (h < 8)       { off = h * 256;                w = qw[tid]; }
    else if (h < 10) { off = 2048 + (h - 8) * 256;   w = kw[tid]; }
    else             { off = 2560 + (h - 10) * 256; }

    float x = row[off + tid];
    float v = x * x;
#pragma unroll
    for (int o = 16; o > 0; o >>= 1) v += __shfl_xor_sync(0xffffffffu, v, o);
    if ((tid & 31) == 0) red[tid >> 5] = v;
    __syncthreads();
    float ss = 0.f;
#pragma unroll
    for (int i = 0; i < 8; i++) ss += red[i];

    float y = x * rsqrtf(ss * (1.0f / 256.0f) + 1e-6f) * w;

    if (h >= 10) {
        V[((size_t)(b * NKV_ + (h - 10)) * S_ + s) * HD_ + tid] = y;
        return;
    }

    sy[tid] = y;
    __syncthreads();

    if (tid < 128) {
        float invf = powf(1000000.0f, -(float)tid * (1.0f / 128.0f));
        float f    = (float)positions[b * S_ + s] * invf;
        float si, co;
        sincosf(f, &si, &co);
        float x1 = sy[tid];
        float x2 = sy[tid + 128];
        float o1 = x1 * co - x2 * si;
        float o2 = x2 * co + x1 * si;
        __nv_bfloat16 h1, l1, h2, l2;
        split_bf16(o1, h1, l1);
        split_bf16(o2, h2, l2);
        if (h < 8) {
            size_t base = ((size_t)(b * NH_ + h) * S_ + s) * HD_;
            QhO[base + tid] = h1;       QlO[base + tid] = l1;
            QhO[base + tid + 128] = h2; QlO[base + tid + 128] = l2;
        } else {
            size_t base = ((size_t)(b * NKV_ + (h - 8)) * S_ + s) * HD_;
            KhO[base + tid] = h1;       KlO[base + tid] = l1;
            KhO[base + tid + 128] = h2; KlO[base + tid + 128] = l2;
        }
    }
}

// ---------------------------------------------------------------------------
// Flash attention on HMMA with bf16x3 emulation — ROUND-10 VERSION VERBATIM
// (best measured): scalar LDS fragments, double-buffered BK=32 KV,
// 217 KB smem, 1 CTA/SM, heavy-first scheduling.
// ---------------------------------------------------------------------------
#define DWQ     132                     // u32 words per Q/K smem row (264 bf16)
#define QROWB   528                     // bytes per Q/K smem row
#define VROWB   80                      // bytes per Vt smem row (40 bf16)
#define SM_QH   0
#define SM_QL   33792                   // 64*528
#define SM_ST0  67584
#define STG_B   74752                   // K(16896*2) + Vt(20480*2)
#define ST_KH   0
#define ST_KL   16896
#define ST_VTH  33792
#define ST_VTL  54272
#define ATTN_SMEM_TOTAL (SM_ST0 + 2 * STG_B)   // 217088

__global__ __launch_bounds__(128, 1) void attn_mma_k(
    const __nv_bfloat16* __restrict__ Qh, const __nv_bfloat16* __restrict__ Ql,
    const __nv_bfloat16* __restrict__ Kh, const __nv_bfloat16* __restrict__ Kl,
    const __nv_bfloat16* __restrict__ Vth, const __nv_bfloat16* __restrict__ Vtl,
    __nv_bfloat16* __restrict__ Ohi, __nv_bfloat16* __restrict__ Olo)
{
    extern __shared__ char dsm[];
    const int t    = threadIdx.x;
    const int lane = t & 31, w = t >> 5;
    const int gid  = lane >> 2, tig = lane & 3;
    const int h    = blockIdx.y, b = blockIdx.z;
    const int qt   = gridDim.x - 1 - blockIdx.x;   // heavy tiles first
    const int q0   = qt * 64;
    const int kvh  = h >> 2;
    const uint32_t smb = smem_u32(dsm);

    const __nv_bfloat16* qhg = Qh + ((size_t)(b * NH_ + h) * S_ + q0) * HD_;
    const __nv_bfloat16* qlg = Ql + ((size_t)(b * NH_ + h) * S_ + q0) * HD_;
    const __nv_bfloat16* khg = Kh + (size_t)(b * NKV_ + kvh) * S_ * HD_;
    const __nv_bfloat16* klg = Kl + (size_t)(b * NKV_ + kvh) * S_ * HD_;
    const __nv_bfloat16* vhg = Vth + (size_t)(b * NKV_ + kvh) * HD_ * S_;
    const __nv_bfloat16* vlg = Vtl + (size_t)(b * NKV_ + kvh) * HD_ * S_;

    // ---- stage Q (hi+lo): 64 rows x 256 bf16 each ----
#pragma unroll
    for (int i = 0; i < 16; i++) {
        const int j = i * 128 + t;             // 0..2047
        const int r = j >> 5, c = j & 31;
        CP_ASYNC16(smb + SM_QH + r * QROWB + c * 16, qhg + (size_t)r * HD_ + c * 8);
        CP_ASYNC16(smb + SM_QL + r * QROWB + c * 16, qlg + (size_t)r * HD_ + c * 8);
    }

    const int nt = qt * 2 + 2;                // K-tiles of 32

    auto issueKV = [&](int kt) {
        const uint32_t st = smb + SM_ST0 + (kt & 1) * STG_B;
        const int k0 = kt << 5;
#pragma unroll
        for (int i = 0; i < 8; i++) {
            const int j = i * 128 + t;         // 0..1023
            const int r = j >> 5, c = j & 31;  // K: row, 8-elt chunk
            CP_ASYNC16(st + ST_KH + r * QROWB + c * 16,
                       khg + (size_t)(k0 + r) * HD_ + c * 8);
            CP_ASYNC16(st + ST_KL + r * QROWB + c * 16,
                       klg + (size_t)(k0 + r) * HD_ + c * 8);
            const int vr = j >> 2, vc = j & 3; // Vt: row d, 8-elt chunk
            CP_ASYNC16(st + ST_VTH + vr * VROWB + vc * 16,
                       vhg + (size_t)vr * S_ + k0 + vc * 8);
            CP_ASYNC16(st + ST_VTL + vr * VROWB + vc * 16,
                       vlg + (size_t)vr * S_ + k0 + vc * 8);
        }
    };

    issueKV(0); CP_COMMIT();

    float O[32][4];
#pragma unroll
    for (int n = 0; n < 32; n++)
#pragma unroll
        for (int i = 0; i < 4; i++) O[n][i] = 0.f;
    float m0 = -1e30f, m1 = -1e30f, l0 = 0.f, l1 = 0.f;

    const int ar0 = (w * 16 + gid) * DWQ;
    const int ar1 = ar0 + 8 * DWQ;
    const uint32_t* QHW = (const uint32_t*)(dsm + SM_QH);
    const uint32_t* QLW = (const uint32_t*)(dsm + SM_QL);

    for (int kt = 0; kt < nt; kt++) {
        const bool more = (kt + 1 < nt);
        if (more) { issueKV(kt + 1); CP_COMMIT(); }
        if (more) CP_WAIT1(); else CP_WAIT0();
        __syncthreads();

        const char* st = dsm + SM_ST0 + (kt & 1) * STG_B;
        const uint32_t* KHW = (const uint32_t*)(st + ST_KH);
        const uint32_t* KLW = (const uint32_t*)(st + ST_KL);
        const uint32_t* VHW = (const uint32_t*)(st + ST_VTH);
        const uint32_t* VLW = (const uint32_t*)(st + ST_VTL);
        const int k0 = kt << 5;

        // ---- S = Q K^T (bf16x3, two accumulator sets for ILP) ----
        float S1[4][4], S2[4][4];
#pragma unroll
        for (int j = 0; j < 4; j++)
#pragma unroll
            for (int i = 0; i < 4; i++) { S1[j][i] = 0.f; S2[j][i] = 0.f; }

#pragma unroll
        for (int ks = 0; ks < 16; ks++) {
            const int kwd = ks * 8 + tig;
            const uint32_t ah0 = QHW[ar0 + kwd], ah1 = QHW[ar1 + kwd];
            const uint32_t ah2 = QHW[ar0 + kwd + 4], ah3 = QHW[ar1 + kwd + 4];
            const uint32_t al0 = QLW[ar0 + kwd], al1 = QLW[ar1 + kwd];
            const uint32_t al2 = QLW[ar0 + kwd + 4], al3 = QLW[ar1 + kwd + 4];
#pragma unroll
            for (int j = 0; j < 4; j++) {
                const int bo = (8 * j + gid) * DWQ + kwd;
                const uint32_t bh0 = KHW[bo], bh1 = KHW[bo + 4];
                const uint32_t bl0 = KLW[bo], bl1 = KLW[bo + 4];
                mma_bf16(S1[j][0], S1[j][1], S1[j][2], S1[j][3],
                         ah0, ah1, ah2, ah3, bh0, bh1);
                mma_bf16(S2[j][0], S2[j][1], S2[j][2], S2[j][3],
                         ah0, ah1, ah2, ah3, bl0, bl1);
                mma_bf16(S2[j][0], S2[j][1], S2[j][2], S2[j][3],
                         al0, al1, al2, al3, bh0, bh1);
            }
        }

        // ---- online softmax ----
        float p[4][4];
        const bool needmask = (k0 + 31) > (q0 + w * 16);
        float tm0 = -1e30f, tm1 = -1e30f;
#pragma unroll
        for (int j = 0; j < 4; j++) {
#pragma unroll
            for (int i = 0; i < 4; i++) {
                float s = S1[j][i] + S2[j][i];
                if (needmask) {
                    const int col = k0 + 8 * j + 2 * tig + (i & 1);
                    const int row = q0 + w * 16 + gid + ((i >= 2) ? 8 : 0);
                    if (col > row) s = -1e30f;
                }
                p[j][i] = s;
                if (i < 2) tm0 = fmaxf(tm0, s); else tm1 = fmaxf(tm1, s);
            }
        }
        tm0 = fmaxf(tm0, __shfl_xor_sync(0xffffffffu, tm0, 1));
        tm0 = fmaxf(tm0, __shfl_xor_sync(0xffffffffu, tm0, 2));
        tm1 = fmaxf(tm1, __shfl_xor_sync(0xffffffffu, tm1, 1));
        tm1 = fmaxf(tm1, __shfl_xor_sync(0xffffffffu, tm1, 2));

        const float mn0 = fmaxf(m0, tm0), mn1 = fmaxf(m1, tm1);
        const float a0 = __expf(m0 - mn0), a1 = __expf(m1 - mn1);

        float sum0 = 0.f, sum1 = 0.f;
#pragma unroll
        for (int j = 0; j < 4; j++) {
            p[j][0] = __expf(p[j][0] - mn0); sum0 += p[j][0];
            p[j][1] = __expf(p[j][1] - mn0); sum0 += p[j][1];
            p[j][2] = __expf(p[j][2] - mn1); sum1 += p[j][2];
            p[j][3] = __expf(p[j][3] - mn1); sum1 += p[j][3];
        }
        sum0 += __shfl_xor_sync(0xffffffffu, sum0, 1);
        sum0 += __shfl_xor_sync(0xffffffffu, sum0, 2);
        sum1 += __shfl_xor_sync(0xffffffffu, sum1, 1);
        sum1 += __shfl_xor_sync(0xffffffffu, sum1, 2);

        l0 = l0 * a0 + sum0;  m0 = mn0;
        l1 = l1 * a1 + sum1;  m1 = mn1;

#pragma unroll
        for (int n = 0; n < 32; n++) {
            O[n][0] *= a0; O[n][1] *= a0;
            O[n][2] *= a1; O[n][3] *= a1;
        }

        // ---- P fragments (hi/lo split, direct from registers) ----
        uint32_t ph[2][4], pl[2][4];
#pragma unroll
        for (int kk = 0; kk < 2; kk++) {
#pragma unroll
            for (int q = 0; q < 4; q++) {
                const int j = 2 * kk + (q >> 1);
                const int i0 = (q & 1) * 2;
                __nv_bfloat16 h0, lo0, h1, lo1;
                split_bf16(p[j][i0], h0, lo0);
                split_bf16(p[j][i0 + 1], h1, lo1);
                ph[kk][q] = pack2(h0, h1);
                pl[kk][q] = pack2(lo0, lo1);
            }
        }

        // ---- O += P V (bf16x3) ----
#pragma unroll
        for (int n = 0; n < 32; n++) {
#pragma unroll
            for (int kk = 0; kk < 2; kk++) {
                const int bo = (8 * n + gid) * 20 + kk * 8 + tig;
                const uint32_t bh0 = VHW[bo], bh1 = VHW[bo + 4];
                const uint32_t bl0 = VLW[bo], bl1 = VLW[bo + 4];
                mma_bf16(O[n][0], O[n][1], O[n][2], O[n][3],
                         ph[kk][0], ph[kk][1], ph[kk][2], ph[kk][3], bh0, bh1);
                mma_bf16(O[n][0], O[n][1], O[n][2], O[n][3],
                         ph[kk][0], ph[kk][1], ph[kk][2], ph[kk][3], bl0, bl1);
                mma_bf16(O[n][0], O[n][1], O[n][2], O[n][3],
                         pl[kk][0], pl[kk][1], pl[kk][2], pl[kk][3], bh0, bh1);
            }
        }
        __syncthreads();
    }

    // ---- epilogue: O/l -> bf16 hi/lo -> global ----
    const float inv0 = 1.f / l0, inv1 = 1.f / l1;
    const size_t ro0 = (size_t)(b * S_ + q0 + w * 16 + gid) * (NH_ * HD_)
                       + h * HD_;
    const size_t ro1 = ro0 + (size_t)8 * (NH_ * HD_);
#pragma unroll
    for (int n = 0; n < 32; n++) {
        const int col = 8 * n + 2 * tig;
        __nv_bfloat16 h0, lo0, h1, lo1;
        split_bf16(O[n][0] * inv0, h0, lo0);
        split_bf16(O[n][1] * inv0, h1, lo1);
        *(uint32_t*)(Ohi + ro0 + col) = pack2(h0, h1);
        *(uint32_t*)(Olo + ro0 + col) = pack2(lo0, lo1);
        split_bf16(O[n][2] * inv1, h0, lo0);
        split_bf16(O[n][3] * inv1, h1, lo1);
        *(uint32_t*)(Ohi + ro1 + col) = pack2(h0, h1);
        *(uint32_t*)(Olo + ro1 + col) = pack2(lo0, lo1);
    }
}

// ---------------------------------------------------------------------------
// Launch
// ---------------------------------------------------------------------------
extern "C" void kernel_launch(void* const* d_in, const int* in_sizes, int n_in,
                              void* d_out, int out_size)
{
    const float* hidden    = (const float*)d_in[0];
    const int*   positions = (const int*)  d_in[1];
    const float* w_qkv     = (const float*)d_in[2];
    const float* w_o       = (const float*)d_in[3];
    const float* q_norm_w  = (const float*)d_in[4];
    const float* k_norm_w  = (const float*)d_in[5];
    float*       out       = (float*)d_out;

    float *qkv, *V;
    __nv_bfloat16 *qh, *ql, *kh, *kl, *vth, *vtl;
    __nv_bfloat16 *hidH, *hidL, *attH, *attL, *wqkH, *wqkL, *woH, *woL;
    cudaGetSymbolAddress((void**)&qkv,  g_qkv);
    cudaGetSymbolAddress((void**)&V,    g_v);
    cudaGetSymbolAddress((void**)&qh,   g_qh);
    cudaGetSymbolAddress((void**)&ql,   g_ql);
    cudaGetSymbolAddress((void**)&kh,   g_kh);
    cudaGetSymbolAddress((void**)&kl,   g_kl);
    cudaGetSymbolAddress((void**)&vth,  g_vth);
    cudaGetSymbolAddress((void**)&vtl,  g_vtl);
    cudaGetSymbolAddress((void**)&hidH, g_hid_hi);
    cudaGetSymbolAddress((void**)&hidL, g_hid_lo);
    cudaGetSymbolAddress((void**)&attH, g_attn_hi);
    cudaGetSymbolAddress((void**)&attL, g_attn_lo);
    cudaGetSymbolAddress((void**)&wqkH, g_wqkT_hi);
    cudaGetSymbolAddress((void**)&wqkL, g_wqkT_lo);
    cudaGetSymbolAddress((void**)&woH,  g_woT_hi);
    cudaGetSymbolAddress((void**)&woL,  g_woT_lo);

    const int GEMM_SMEM = NSTAGE * STAGE_B;      // 98304
    cudaFuncSetAttribute(gemm_bf16x3_k,
        cudaFuncAttributeMaxDynamicSharedMemorySize, GEMM_SMEM);
    cudaFuncSetAttribute(attn_mma_k,
        cudaFuncAttributeMaxDynamicSharedMemorySize, ATTN_SMEM_TOTAL);

    // 0) operand preparation
    {
        const int n4 = (MROWS * HIDDEN_) / 4;
        split_k<<<(n4 + 255) / 256, 256>>>(hidden, hidH, hidL, n4);
    }
    transpose_split_k<<<dim3(QKV_N / 32, HIDDEN_ / 32), dim3(32, 8)>>>(
        w_qkv, wqkH, wqkL, HIDDEN_, QKV_N);
    transpose_split_k<<<dim3((NH_ * HD_) / 32, HIDDEN_ / 32), dim3(32, 8)>>>(
        w_o, woH, woL, HIDDEN_, NH_ * HD_);

    // 1) QKV projection
    gemm_bf16x3_k<<<dim3(QKV_N / 128, MROWS / 128), 256, GEMM_SMEM>>>(
        hidH, hidL, wqkH, wqkL, qkv, MROWS, QKV_N, HIDDEN_);

    // 2) rmsnorm + rope -> Q/K bf16 hi/lo, V fp32
    qkv_post_k<<<dim3(12, S_, B_), 256>>>(
        qkv, positions, q_norm_w, k_norm_w, qh, ql, kh, kl, V);

    // 2b) V^T split, all slices in one launch
    vt_split_k<<<dim3(HD_ / 32, S_ / 32, B_ * NKV_), dim3(32, 8)>>>(
        V, vth, vtl);

    // 3) causal attention (round-10 config, best measured)
    attn_mma_k<<<dim3(S_ / 64, NH_, B_), 128, ATTN_SMEM_TOTAL>>>(
        qh, ql, kh, kl, vth, vtl, attH, attL);

    // 4) output projection
    gemm_bf16x3_k<<<dim3((NH_ * HD_) / 128, MROWS / 128), 256, GEMM_SMEM>>>(
        attH, attL, woH, woL, out, MROWS, NH_ * HD_, HIDDEN_);
}